// round 2
// baseline (speedup 1.0000x reference)
#include <cuda_runtime.h>
#include <math.h>

typedef unsigned long long u64;
#define Bq 32
#define Dq 128
#define Hq 256
#define Oq 10

// Scratch (allocation-free rule: __device__ globals)
__device__ float g_C[Hq*Hq];        // W1^T W1
__device__ float g_K[Bq*Oq*Hq];     // K[b][o][g]
__device__ float g_u[Bq*Hq];
__device__ float g_G2[Bq*Oq*Oq];
__device__ float g_num[Bq*Dq];
__device__ float g_nv[Bq];
__device__ float g_part[Bq*8];
__device__ int   g_cnt[Bq];         // zero-init; reset after use each run

// ---- f32x2 packed helpers (sm_103a) ----
__device__ __forceinline__ u64 pk2(float x, float y){ u64 r; asm("mov.b64 %0,{%1,%2};" : "=l"(r) : "f"(x),"f"(y)); return r; }
__device__ __forceinline__ u64 fma2(u64 a,u64 b,u64 c){ u64 d; asm("fma.rn.f32x2 %0,%1,%2,%3;" : "=l"(d) : "l"(a),"l"(b),"l"(c)); return d; }
__device__ __forceinline__ void up2(u64 a, float&x, float&y){ asm("mov.b64 {%0,%1},%2;" : "=f"(x),"=f"(y) : "l"(a)); }
__device__ __forceinline__ float hadd2(u64 a){ float x,y; up2(a,x,y); return x+y; }

// ============ Launch 1: blocks [0,256) = C = W1^T W1 ; blocks [256,288) = per-batch preamble ============
__global__ void k1(const float* __restrict__ t, const float* __restrict__ sb,
                   const float* __restrict__ x0, const float* __restrict__ x1,
                   const float* __restrict__ W1, const float* __restrict__ b1,
                   const float* __restrict__ W2)
{
    int tid = threadIdx.x;
    if (blockIdx.x < Hq) {                      // ---- C block ----
        int h = blockIdx.x;
        float acc = 0.f;
        #pragma unroll 8
        for (int d = 0; d < Dq; d++) acc += W1[d*Hq+h] * W1[d*Hq+tid];
        g_C[h*Hq+tid] = acc;
        return;
    }
    // ---- batch preamble block (does NOT touch g_C: K built via A = (s.W2)^T W1^T) ----
    int b = blockIdx.x - Hq;
    __shared__ __align__(16) float2 sxv[Dq];      // (x, v)
    __shared__ __align__(16) float ssw2[Hq*12];   // s_h*W2[h][o], padded
    __shared__ __align__(16) float sKT[Hq*12];    // K^T[g][o], padded
    __shared__ __align__(16) float sA[Dq*12];     // A[d][o], padded
    __shared__ float ss[Hq], su[Hq], sw[Hq], sp[Hq], sc[16];

    float tt = t[0];
    float window = 4.f*tt*(1.f-tt);
    if (tid < Dq) {
        float dev = sb[b*Dq + tid];
        float a0v = x0[b*Dq + tid];
        float xx = a0v + tt*(x1[b*Dq+tid]-a0v) + window*dev;
        float vv = sb[Bq*Dq + b*Dq + tid];
        sxv[tid] = make_float2(xx, vv);
    }
    __syncthreads();

    // z_h, w_h packed as f32x2 (thread = h)
    u64 zw = pk2(b1[tid], 0.f);
    const u64* sxv64 = (const u64*)sxv;
    #pragma unroll 4
    for (int d = 0; d < Dq; d++) {
        float wv = W1[d*Hq + tid];
        zw = fma2(sxv64[d], pk2(wv,wv), zw);
    }
    float z, w; up2(zw, z, w);
    float th = tanhf(z);
    float s  = 1.f - th*th;
    float u  = -2.f*th*s;
    ss[tid]=s; su[tid]=u; sw[tid]=w;
    g_u[b*Hq+tid] = u;
    float w2r[Oq];
    #pragma unroll
    for (int o=0;o<Oq;o++){ w2r[o]=W2[tid*Oq+o]; ssw2[tid*12+o]=s*w2r[o]; }
    ssw2[tid*12+10]=0.f; ssw2[tid*12+11]=0.f;

    if (tid < 32) {   // ||v||
        float acc = 0.f;
        for (int d = tid; d < Dq; d += 32) { float v = sxv[d].y; acc += v*v; }
        #pragma unroll
        for (int o = 16; o; o >>= 1) acc += __shfl_xor_sync(~0u, acc, o);
        if (tid == 0) g_nv[b] = sqrtf(acc) + 1e-6f;
    }
    __syncthreads();

    // A[d][o] = sum_h ssw2[h][o] * W1[d][h]   (thread: d = tid&127, o-sextet = tid>>7)
    {
        int d = tid & (Dq-1), obase = (tid >> 7) * 6;
        u64 a0=0, a1=0, a2=0;
        const float* w1r = W1 + d*Hq;
        #pragma unroll 2
        for (int h = 0; h < Hq; h += 4) {
            float4 wq = *(const float4*)(w1r + h);
            const float* base = ssw2 + h*12 + obase;
            u64 bb;
            bb = pk2(wq.x,wq.x);
            a0=fma2(*(const u64*)(base+ 0),bb,a0); a1=fma2(*(const u64*)(base+ 2),bb,a1); a2=fma2(*(const u64*)(base+ 4),bb,a2);
            bb = pk2(wq.y,wq.y);
            a0=fma2(*(const u64*)(base+12),bb,a0); a1=fma2(*(const u64*)(base+14),bb,a1); a2=fma2(*(const u64*)(base+16),bb,a2);
            bb = pk2(wq.z,wq.z);
            a0=fma2(*(const u64*)(base+24),bb,a0); a1=fma2(*(const u64*)(base+26),bb,a1); a2=fma2(*(const u64*)(base+28),bb,a2);
            bb = pk2(wq.w,wq.w);
            a0=fma2(*(const u64*)(base+36),bb,a0); a1=fma2(*(const u64*)(base+38),bb,a1); a2=fma2(*(const u64*)(base+40),bb,a2);
        }
        u64* adst = (u64*)(sA + d*12 + obase);
        adst[0]=a0; adst[1]=a1; adst[2]=a2;   // ob=1 writes o10,o11 pads = 0 (ssw2 pads are 0)
    }
    __syncthreads();

    // K[o][g] = sum_d A[o][d] W1[d][g]   (thread = g)
    {
        int g = tid;
        u64 k0=0,k1v=0,k2v=0,k3=0,k4=0;
        #pragma unroll 4
        for (int d = 0; d < Dq; d++) {
            float wv = W1[d*Hq + g];
            u64 bb = pk2(wv,wv);
            const u64* ap = (const u64*)(sA + d*12);
            k0=fma2(ap[0],bb,k0); k1v=fma2(ap[1],bb,k1v); k2v=fma2(ap[2],bb,k2v);
            k3=fma2(ap[3],bb,k3); k4=fma2(ap[4],bb,k4);
        }
        u64* kdst = (u64*)(sKT + g*12);
        kdst[0]=k0; kdst[1]=k1v; kdst[2]=k2v; kdst[3]=k3; kdst[4]=k4;
        sKT[g*12+10]=0.f; sKT[g*12+11]=0.f;
        float kv[Oq];
        up2(k0,kv[0],kv[1]); up2(k1v,kv[2],kv[3]); up2(k2v,kv[4],kv[5]);
        up2(k3,kv[6],kv[7]); up2(k4,kv[8],kv[9]);
        #pragma unroll
        for (int o=0;o<Oq;o++) g_K[(b*Oq+o)*Hq + g] = kv[o];
    }
    __syncthreads();

    // G2[o][p] = sum_g K[o][g] (s_g W2[g][p]); c_o = sum_h W2[h][o] u_h w_h^2
    if (tid < Oq*Oq) {
        int o = tid/Oq, p = tid%Oq;
        float acc = 0.f;
        for (int g = 0; g < Hq; g++) acc += sKT[g*12+o]*ssw2[g*12+p];
        g_G2[b*Oq*Oq+tid] = acc;
    } else if (tid >= 128 && tid < 128+Oq) {
        int o = tid-128;
        float acc = 0.f;
        for (int h = 0; h < Hq; h++) acc += W2[h*Oq+o]*su[h]*sw[h]*sw[h];
        sc[o] = acc;
    }
    __syncthreads();

    // sp_g = s_g * (W2 c)_g ; num_i = sum_g sp_g W1[i][g]
    {
        float p = 0.f;
        #pragma unroll
        for (int o=0;o<Oq;o++) p += w2r[o]*sc[o];
        sp[tid] = ss[tid]*p;
    }
    __syncthreads();
    {
        int warp = tid>>5, lane = tid&31;
        for (int r = 0; r < 16; r++) {
            int i = warp*16 + r;
            float acc = 0.f;
            #pragma unroll
            for (int g = lane; g < Hq; g += 32) acc += sp[g]*W1[i*Hq+g];
            #pragma unroll
            for (int o = 16; o; o >>= 1) acc += __shfl_xor_sync(~0u, acc, o);
            if (lane == 0) g_num[b*Dq+i] = acc;
        }
    }
}

// ============ Launch 2: pair reduction (32 b x 8 splits) + last-block finalize + output ============
__global__ void k2(const float* __restrict__ W2, const float* __restrict__ sb,
                   float* __restrict__ out)
{
    int b = blockIdx.x >> 3, split = blockIdx.x & 7;
    int h0 = split*32;
    int g = threadIdx.x;
    __shared__ __align__(16) float sWU[32*12];
    __shared__ __align__(16) float sKT[32*12];
    __shared__ float sG2[Oq*Oq];
    __shared__ float sred[8];
    __shared__ float sscale;
    __shared__ int slast;

    if (split == 0 && g < Dq)                         // velocity half (no dependency)
        out[b*Dq + g] = sb[Bq*Dq + b*Dq + g];

    if (g < Oq*Oq) sG2[g] = g_G2[b*Oq*Oq+g];
    if (g >= 128 && g < 160) {
        int hh = g-128, h = h0+hh;
        #pragma unroll
        for (int o=0;o<Oq;o++){ sWU[hh*12+o]=W2[h*Oq+o]; sKT[hh*12+o]=g_K[(b*Oq+o)*Hq+h]; }
        sWU[hh*12+10]=g_u[b*Hq+h]; sWU[hh*12+11]=0.f;
        sKT[hh*12+10]=0.f; sKT[hh*12+11]=0.f;
    }
    float u_g = g_u[b*Hq+g];
    float w2g[Oq], kc[Oq];
    #pragma unroll
    for (int o=0;o<Oq;o++){ kc[o]=g_K[(b*Oq+o)*Hq+g]; w2g[o]=W2[g*Oq+o]; }
    __syncthreads();

    float wgs[Oq];
    #pragma unroll
    for (int o=0;o<Oq;o++){
        float a = 0.f;
        #pragma unroll
        for (int p=0;p<Oq;p++) a += sG2[o*Oq+p]*w2g[p];
        wgs[o] = a;
    }
    u64 wgp[5], kcp[5], w2p[5];
    #pragma unroll
    for (int i=0;i<5;i++){ wgp[i]=pk2(wgs[2*i],wgs[2*i+1]); kcp[i]=pk2(kc[2*i],kc[2*i+1]); w2p[i]=pk2(w2g[2*i],w2g[2*i+1]); }

    float acc = 0.f;
    #pragma unroll 2
    for (int hh = 0; hh < 32; hh++) {
        int h = h0 + hh;
        float c = g_C[h*Hq + g];
        const u64* pa = (const u64*)(sWU + hh*12);
        const u64* pb = (const u64*)(sKT + hh*12);
        u64 q2=0, r2=0, s2=0;
        #pragma unroll
        for (int i=0;i<5;i++){
            q2 = fma2(pa[i], wgp[i], q2);
            r2 = fma2(pa[i], kcp[i], r2);
            s2 = fma2(pb[i], w2p[i], s2);
        }
        float qq = hadd2(q2), rhg = hadd2(r2), rgh = hadd2(s2);
        float uh = sWU[hh*12+10];
        acc += uh*(c*(c*qq + rhg*rgh));
    }
    acc *= u_g;
    #pragma unroll
    for (int o = 16; o; o >>= 1) acc += __shfl_xor_sync(~0u, acc, o);
    if ((g&31) == 0) sred[g>>5] = acc;
    __syncthreads();
    if (g == 0) {
        float ttl = 0.f;
        #pragma unroll
        for (int i=0;i<8;i++) ttl += sred[i];
        g_part[b*8+split] = ttl;
        __threadfence();
        int old = atomicAdd(&g_cnt[b], 1);   // int atomic: deterministic values
        slast = (old == 7);
    }
    __syncthreads();
    if (slast) {            // last block of this batch finalizes (fixed-order float sum)
        if (g == 0) {
            __threadfence();
            float n2 = 0.f;
            #pragma unroll
            for (int k2i=0;k2i<8;k2i++) n2 += g_part[b*8+k2i];
            n2 *= 2.f;
            float nF = sqrtf(fmaxf(n2, 0.f)) + 1e-6f;
            sscale = -1.f/(nF * g_nv[b]);
            g_cnt[b] = 0;   // reset for next replay
        }
        __syncthreads();
        if (g < Dq)
            out[Bq*Dq + b*Dq + g] = g_num[b*Dq+g]*sscale - 0.1f*sb[b*Dq+g];
    }
}

extern "C" void kernel_launch(void* const* d_in, const int* in_sizes, int n_in,
                              void* d_out, int out_size) {
    const float* t  = (const float*)d_in[0];
    const float* sb = (const float*)d_in[1];
    const float* x0 = (const float*)d_in[2];
    const float* x1 = (const float*)d_in[3];
    const float* W1 = (const float*)d_in[4];
    const float* b1 = (const float*)d_in[5];
    const float* W2 = (const float*)d_in[6];
    float* out = (float*)d_out;

    k1<<<Hq + Bq, Hq>>>(t, sb, x0, x1, W1, b1, W2);
    k2<<<Bq*8, Hq>>>(W2, sb, out);
}

// round 3
// speedup vs baseline: 1.4162x; 1.4162x over previous
#include <cuda_runtime.h>
#include <math.h>

typedef unsigned long long u64;
#define Bq 32
#define Dq 128
#define Hq 256
#define Oq 10
#define NCT 36            // C tile blocks (upper triangle of 8x8 tiles of 32)
#define NS  16            // h-splits per batch in pair phase
#define NP  (Bq*NS)       // 512 pair blocks

// Scratch (allocation-free rule: __device__ globals; zero-initialized)
__device__ float g_C[Hq*Hq];
__device__ float g_K[Bq*Oq*Hq];
__device__ float g_u[Bq*Hq];
__device__ float g_G2[Bq*Oq*Oq];
__device__ float g_num[Bq*Dq];
__device__ float g_nv[Bq];
__device__ float g_part[Bq*NS];
__device__ int   g_cnt[Bq];
__device__ int   g_cdone;
__device__ int   g_bdone[Bq];
__device__ int   g_all;

// ---- f32x2 packed helpers (sm_103a) ----
__device__ __forceinline__ u64 pk2(float x, float y){ u64 r; asm("mov.b64 %0,{%1,%2};" : "=l"(r) : "f"(x),"f"(y)); return r; }
__device__ __forceinline__ u64 fma2(u64 a,u64 b,u64 c){ u64 d; asm("fma.rn.f32x2 %0,%1,%2,%3;" : "=l"(d) : "l"(a),"l"(b),"l"(c)); return d; }
__device__ __forceinline__ void up2(u64 a, float&x, float&y){ asm("mov.b64 {%0,%1},%2;" : "=f"(x),"=f"(y) : "l"(a)); }
__device__ __forceinline__ float hadd2(u64 a){ float x,y; up2(a,x,y); return x+y; }
__device__ __forceinline__ int ldacq(const int* p){
    int v; asm volatile("ld.global.acquire.gpu.b32 %0, [%1];" : "=r"(v) : "l"(p) : "memory"); return v;
}
__device__ __forceinline__ void strel(int* p, int v){
    asm volatile("st.global.release.gpu.b32 [%0], %1;" :: "l"(p), "r"(v) : "memory");
}

__global__ void __launch_bounds__(256, 4)
mega(const float* __restrict__ t,  const float* __restrict__ sb,
     const float* __restrict__ x0, const float* __restrict__ x1,
     const float* __restrict__ W1, const float* __restrict__ b1,
     const float* __restrict__ W2, float* __restrict__ out)
{
    __shared__ __align__(16) float SH[8448];
    __shared__ float sred[8];
    __shared__ float sscale;
    __shared__ int   sflag;
    int tid = threadIdx.x;
    int bx  = blockIdx.x;

    // ================= Phase C: 36 tile blocks, C = W1^T W1 (symmetric) =================
    if (bx < NCT) {
        int r = bx, ti = 0;
        while (r >= 8 - ti) { r -= 8 - ti; ti++; }
        int tj = ti + r;
        float* shA = SH;           // [128][33]
        float* shB = SH + 4224;    // [128][33]
        for (int i = tid; i < 4096; i += 256) {
            int d = i >> 5, col = i & 31;
            shA[d*33+col] = W1[d*Hq + ti*32 + col];
            shB[d*33+col] = W1[d*Hq + tj*32 + col];
        }
        __syncthreads();
        int jb = tid & 31, a0 = (tid >> 5) * 4;
        float acc0=0.f, acc1=0.f, acc2=0.f, acc3=0.f;
        #pragma unroll 4
        for (int d = 0; d < Dq; d++) {
            float bv = shB[d*33 + jb];
            acc0 += shA[d*33 + a0+0]*bv;
            acc1 += shA[d*33 + a0+1]*bv;
            acc2 += shA[d*33 + a0+2]*bv;
            acc3 += shA[d*33 + a0+3]*bv;
        }
        int h0 = ti*32, g0 = tj*32;
        g_C[(h0+a0+0)*Hq + g0+jb] = acc0;
        g_C[(h0+a0+1)*Hq + g0+jb] = acc1;
        g_C[(h0+a0+2)*Hq + g0+jb] = acc2;
        g_C[(h0+a0+3)*Hq + g0+jb] = acc3;
        if (ti != tj) {   // mirror (C symmetric)
            g_C[(g0+jb)*Hq + h0+a0+0] = acc0;
            g_C[(g0+jb)*Hq + h0+a0+1] = acc1;
            g_C[(g0+jb)*Hq + h0+a0+2] = acc2;
            g_C[(g0+jb)*Hq + h0+a0+3] = acc3;
        }
        __threadfence();
        __syncthreads();
        if (tid == 0) atomicAdd(&g_cdone, 1);
        return;
    }

    // ================= Phase P: 32 per-batch preamble blocks =================
    if (bx < NCT + Bq) {
        int b = bx - NCT;
        float*  ssw2 = SH;                       // [256][12] s_h*W2[h][o]
        float*  sKT  = SH + 3072;                // [256][12] K^T[g][o]
        float2* sxv  = (float2*)(SH + 6144);     // (x,v)[128]
        float*  ss   = SH + 6400;
        float*  su   = SH + 6656;
        float*  sw_  = SH + 6912;
        float*  sp   = SH + 7168;
        float*  sc   = SH + 7424;

        float tt = t[0];
        float window = 4.f*tt*(1.f-tt);
        if (tid < Dq) {
            float dev = sb[b*Dq + tid];
            float a0v = x0[b*Dq + tid];
            sxv[tid] = make_float2(a0v + tt*(x1[b*Dq+tid]-a0v) + window*dev,
                                   sb[Bq*Dq + b*Dq + tid]);
        }
        __syncthreads();

        // z_h, w_h packed f32x2 (thread = h; W1 column reads coalesced)
        u64 zw = pk2(b1[tid], 0.f);
        const u64* sxv64 = (const u64*)sxv;
        #pragma unroll 4
        for (int d = 0; d < Dq; d++) {
            float wv = W1[d*Hq + tid];
            zw = fma2(sxv64[d], pk2(wv,wv), zw);
        }
        float z, w; up2(zw, z, w);
        float th = tanhf(z);
        float s  = 1.f - th*th;
        float u  = -2.f*th*s;
        ss[tid]=s; su[tid]=u; sw_[tid]=w;
        g_u[b*Hq+tid] = u;
        float w2r[Oq];
        #pragma unroll
        for (int o=0;o<Oq;o++){ w2r[o]=W2[tid*Oq+o]; ssw2[tid*12+o]=s*w2r[o]; }
        ssw2[tid*12+10]=0.f; ssw2[tid*12+11]=0.f;

        if (tid < 32) {   // ||v||
            float acc = 0.f;
            for (int d = tid; d < Dq; d += 32) { float v = sxv[d].y; acc += v*v; }
            #pragma unroll
            for (int o = 16; o; o >>= 1) acc += __shfl_xor_sync(~0u, acc, o);
            if (tid == 0) g_nv[b] = sqrtf(acc) + 1e-6f;
        }
        // wait for C (overlapped with the work above)
        if (tid == 0) { while (ldacq(&g_cdone) < NCT) __nanosleep(64); }
        __syncthreads();

        // K[o][g] = sum_h (s_h W2[h][o]) C[h][g]   (thread = g; coalesced C rows, prefetch 8)
        {
            u64 k0=0,k1v=0,k2v=0,k3=0,k4=0;
            for (int h = 0; h < Hq; h += 8) {
                float c[8];
                #pragma unroll
                for (int i=0;i<8;i++) c[i] = g_C[(h+i)*Hq + tid];
                #pragma unroll
                for (int i=0;i<8;i++) {
                    u64 bb = pk2(c[i],c[i]);
                    const u64* pp = (const u64*)(ssw2 + (h+i)*12);
                    k0=fma2(pp[0],bb,k0); k1v=fma2(pp[1],bb,k1v); k2v=fma2(pp[2],bb,k2v);
                    k3=fma2(pp[3],bb,k3); k4=fma2(pp[4],bb,k4);
                }
            }
            u64* kdst = (u64*)(sKT + tid*12);
            kdst[0]=k0; kdst[1]=k1v; kdst[2]=k2v; kdst[3]=k3; kdst[4]=k4;
            sKT[tid*12+10]=0.f; sKT[tid*12+11]=0.f;
            float kv[Oq];
            up2(k0,kv[0],kv[1]); up2(k1v,kv[2],kv[3]); up2(k2v,kv[4],kv[5]);
            up2(k3,kv[6],kv[7]); up2(k4,kv[8],kv[9]);
            #pragma unroll
            for (int o=0;o<Oq;o++) g_K[(b*Oq+o)*Hq + tid] = kv[o];
        }
        __syncthreads();

        // G2[o][p] and c_o
        if (tid < Oq*Oq) {
            int o = tid/Oq, p = tid%Oq;
            float acc = 0.f;
            for (int g = 0; g < Hq; g++) acc += sKT[g*12+o]*ssw2[g*12+p];
            g_G2[b*Oq*Oq + tid] = acc;
        } else if (tid >= 128 && tid < 128+Oq) {
            int o = tid-128;
            float acc = 0.f;
            for (int h = 0; h < Hq; h++) acc += W2[h*Oq+o]*su[h]*sw_[h]*sw_[h];
            sc[o] = acc;
        }
        __syncthreads();

        {   // sp_g = s_g * (W2 c)_g
            float p = 0.f;
            #pragma unroll
            for (int o=0;o<Oq;o++) p += w2r[o]*sc[o];
            sp[tid] = ss[tid]*p;
        }
        __syncthreads();
        {   // num_i = sum_g sp_g W1[i][g]  (warp-per-row, coalesced)
            int warp = tid>>5, lane = tid&31;
            for (int r = 0; r < 16; r++) {
                int i = warp*16 + r;
                float acc = 0.f;
                #pragma unroll
                for (int g = lane; g < Hq; g += 32) acc += sp[g]*W1[i*Hq+g];
                #pragma unroll
                for (int o = 16; o; o >>= 1) acc += __shfl_xor_sync(~0u, acc, o);
                if (lane == 0) g_num[b*Dq+i] = acc;
            }
        }
        __threadfence();
        __syncthreads();
        if (tid == 0) strel(&g_bdone[b], 1);
        return;
    }

    // ================= Phase Q: 512 pair-reduction blocks =================
    {
        int pb = bx - NCT - Bq;
        int b = pb >> 4, split = pb & (NS-1);
        int h0 = split * 16;
        int g = tid;
        float* sWU  = SH;         // [16][12] W2 row + u_h at [10]
        float* sKTp = SH + 192;   // [16][12] K[:,h]
        float* sG2  = SH + 384;   // [100]

        if (split == 0 && tid < Dq)   // velocity half: no dependency, do before spin
            out[b*Dq + tid] = sb[Bq*Dq + b*Dq + tid];

        if (tid == 0) { while (ldacq(&g_bdone[b]) == 0) __nanosleep(64); }
        __syncthreads();

        if (tid < Oq*Oq) sG2[tid] = g_G2[b*Oq*Oq + tid];
        if (tid >= 128 && tid < 144) {
            int hh = tid - 128, h = h0 + hh;
            #pragma unroll
            for (int o=0;o<Oq;o++){ sWU[hh*12+o]=W2[h*Oq+o]; sKTp[hh*12+o]=g_K[(b*Oq+o)*Hq+h]; }
            sWU[hh*12+10]=g_u[b*Hq+h]; sWU[hh*12+11]=0.f;
            sKTp[hh*12+10]=0.f; sKTp[hh*12+11]=0.f;
        }
        float u_g = g_u[b*Hq + g];
        float kc[Oq], w2g[Oq];
        #pragma unroll
        for (int o=0;o<Oq;o++){ kc[o]=g_K[(b*Oq+o)*Hq+g]; w2g[o]=W2[g*Oq+o]; }
        __syncthreads();

        float wgs[Oq];
        #pragma unroll
        for (int o=0;o<Oq;o++){
            float a = 0.f;
            #pragma unroll
            for (int p=0;p<Oq;p++) a += sG2[o*Oq+p]*w2g[p];
            wgs[o] = a;
        }
        u64 wgp[5], kcp[5], w2p[5];
        #pragma unroll
        for (int i=0;i<5;i++){ wgp[i]=pk2(wgs[2*i],wgs[2*i+1]); kcp[i]=pk2(kc[2*i],kc[2*i+1]); w2p[i]=pk2(w2g[2*i],w2g[2*i+1]); }

        float c[16];
        #pragma unroll
        for (int i=0;i<16;i++) c[i] = g_C[(h0+i)*Hq + g];   // coalesced, MLP=16

        float acc = 0.f;
        #pragma unroll
        for (int hh = 0; hh < 16; hh++) {
            const u64* pa  = (const u64*)(sWU  + hh*12);
            const u64* pb2 = (const u64*)(sKTp + hh*12);
            u64 q2=0, r2=0, s2=0;
            #pragma unroll
            for (int i=0;i<5;i++){
                q2 = fma2(pa[i],  wgp[i], q2);
                r2 = fma2(pa[i],  kcp[i], r2);
                s2 = fma2(pb2[i], w2p[i], s2);
            }
            float qq = hadd2(q2), rhg = hadd2(r2), rgh = hadd2(s2);
            float uh = sWU[hh*12+10];
            float cc = c[hh];
            acc += uh*(cc*(cc*qq + rhg*rgh));
        }
        acc *= u_g;
        #pragma unroll
        for (int o = 16; o; o >>= 1) acc += __shfl_xor_sync(~0u, acc, o);
        if ((tid&31) == 0) sred[tid>>5] = acc;
        __syncthreads();
        if (tid == 0) {
            float ttl = 0.f;
            #pragma unroll
            for (int i=0;i<8;i++) ttl += sred[i];
            g_part[b*NS + split] = ttl;
            __threadfence();
            int old = atomicAdd(&g_cnt[b], 1);
            sflag = (old == NS-1);
        }
        __syncthreads();
        if (sflag) {   // per-batch finalize (fixed-order float sum — deterministic)
            if (tid == 0) {
                __threadfence();
                float n2 = 0.f;
                #pragma unroll
                for (int k=0;k<NS;k++) n2 += g_part[b*NS + k];
                n2 *= 2.f;
                float nF = sqrtf(fmaxf(n2, 0.f)) + 1e-6f;
                sscale = -1.f/(nF * g_nv[b]);
                g_cnt[b] = 0;                     // reset for next replay
            }
            __syncthreads();
            if (tid < Dq)
                out[Bq*Dq + b*Dq + tid] = g_num[b*Dq+tid]*sscale - 0.1f*sb[b*Dq+tid];
        }
        if (tid == 0) {   // global epilogue: last pair block resets flags for replay
            int old = atomicAdd(&g_all, 1);
            if (old == NP-1) {
                g_cdone = 0;
                #pragma unroll
                for (int i=0;i<Bq;i++) g_bdone[i] = 0;
                g_all = 0;
            }
        }
    }
}

extern "C" void kernel_launch(void* const* d_in, const int* in_sizes, int n_in,
                              void* d_out, int out_size) {
    const float* t  = (const float*)d_in[0];
    const float* sb = (const float*)d_in[1];
    const float* x0 = (const float*)d_in[2];
    const float* x1 = (const float*)d_in[3];
    const float* W1 = (const float*)d_in[4];
    const float* b1 = (const float*)d_in[5];
    const float* W2 = (const float*)d_in[6];
    float* out = (float*)d_out;

    mega<<<NCT + Bq + NP, 256>>>(t, sb, x0, x1, W1, b1, W2, out);
}

// round 4
// speedup vs baseline: 1.8778x; 1.3259x over previous
#include <cuda_runtime.h>
#include <math.h>

typedef unsigned long long u64;
#define Bq 32
#define Dq 128
#define Hq 256
#define Oq 10
#define NCT 36                // C tile blocks (upper-tri of 8x8 tiles of 32)
#define NS  8                 // h-splits per batch in pair phase
#define NP  (Bq*NS)           // 256 pair blocks
#define BX_P (NCT)            // 36  : P blocks start
#define BX_K (NCT+Bq)         // 68  : K blocks start (2 per batch)
#define BX_Q (NCT+Bq+2*Bq)    // 132 : pair blocks start
#define GRID (BX_Q+NP)        // 388 total (< 592 resident capacity -> 1 wave)

// Scratch (allocation-free rule: __device__ globals; zero-initialized)
__device__ float g_C[Hq*Hq];
__device__ float g_K[Bq*Oq*Hq];
__device__ float g_u[Bq*Hq];
__device__ float g_G2p[Bq][2][112];
__device__ float g_G2[Bq*Oq*Oq];
__device__ float g_num[Bq*Dq];
__device__ float g_nv[Bq];
__device__ float g_part[Bq*NS];
__device__ int   g_cdone;
__device__ int   g_kcnt[Bq];
__device__ int   g_bdone[Bq];
__device__ int   g_pdone[Bq];
__device__ int   g_cnt[Bq];
__device__ int   g_all;

// ---- f32x2 packed helpers (sm_103a) ----
__device__ __forceinline__ u64 pk2(float x, float y){ u64 r; asm("mov.b64 %0,{%1,%2};" : "=l"(r) : "f"(x),"f"(y)); return r; }
__device__ __forceinline__ u64 fma2(u64 a,u64 b,u64 c){ u64 d; asm("fma.rn.f32x2 %0,%1,%2,%3;" : "=l"(d) : "l"(a),"l"(b),"l"(c)); return d; }
__device__ __forceinline__ void up2(u64 a, float&x, float&y){ asm("mov.b64 {%0,%1},%2;" : "=f"(x),"=f"(y) : "l"(a)); }
__device__ __forceinline__ float hadd2(u64 a){ float x,y; up2(a,x,y); return x+y; }
__device__ __forceinline__ int ldacq(const int* p){
    int v; asm volatile("ld.global.acquire.gpu.b32 %0, [%1];" : "=r"(v) : "l"(p) : "memory"); return v;
}
__device__ __forceinline__ void strel(int* p, int v){
    asm volatile("st.global.release.gpu.b32 [%0], %1;" :: "l"(p), "r"(v) : "memory");
}

__global__ void __launch_bounds__(256, 4)
mega(const float* __restrict__ t,  const float* __restrict__ sb,
     const float* __restrict__ x0, const float* __restrict__ x1,
     const float* __restrict__ W1, const float* __restrict__ b1,
     const float* __restrict__ W2, float* __restrict__ out)
{
    __shared__ __align__(16) float SH[9600];
    __shared__ float sred[8];
    __shared__ float sscale;
    __shared__ int   sflag;
    int tid = threadIdx.x;
    int bx  = blockIdx.x;

    // ================= Phase C: C = W1^T W1 (36 symmetric tiles) =================
    if (bx < NCT) {
        int r = bx, ti = 0;
        while (r >= 8 - ti) { r -= 8 - ti; ti++; }
        int tj = ti + r;
        float* shA = SH;            // [128][36]
        float* shB = SH + 4608;     // [128][36]
        for (int i = tid; i < 4096; i += 256) {
            int d = i >> 5, col = i & 31;
            shA[d*36+col] = W1[d*Hq + ti*32 + col];
            shB[d*36+col] = W1[d*Hq + tj*32 + col];
        }
        __syncthreads();
        int jb = tid & 31, a0 = (tid >> 5) * 4;
        float acc0=0.f, acc1=0.f, acc2=0.f, acc3=0.f;
        #pragma unroll 4
        for (int d = 0; d < Dq; d++) {
            float4 av = *(const float4*)(shA + d*36 + a0);
            float  bv = shB[d*36 + jb];
            acc0 += av.x*bv; acc1 += av.y*bv; acc2 += av.z*bv; acc3 += av.w*bv;
        }
        int h0 = ti*32, g0 = tj*32;
        g_C[(h0+a0+0)*Hq + g0+jb] = acc0;
        g_C[(h0+a0+1)*Hq + g0+jb] = acc1;
        g_C[(h0+a0+2)*Hq + g0+jb] = acc2;
        g_C[(h0+a0+3)*Hq + g0+jb] = acc3;
        if (ti != tj) {
            g_C[(g0+jb)*Hq + h0+a0+0] = acc0;
            g_C[(g0+jb)*Hq + h0+a0+1] = acc1;
            g_C[(g0+jb)*Hq + h0+a0+2] = acc2;
            g_C[(g0+jb)*Hq + h0+a0+3] = acc3;
        }
        __threadfence();
        __syncthreads();
        if (tid == 0) atomicAdd(&g_cdone, 1);
        return;
    }

    // ================= Phase P: 32 C-free per-batch blocks (overlaps C) =================
    if (bx < BX_K) {
        int b = bx - BX_P;
        float2* sxv = (float2*)SH;        // [128] (x,v)
        float*  ss  = SH + 256;
        float*  sq  = SH + 512;           // u*w^2
        float*  sp  = SH + 768;
        float*  sc  = SH + 1024;          // [16]

        float tt = t[0];
        float window = 4.f*tt*(1.f-tt);
        if (tid < Dq) {
            float dev = sb[b*Dq + tid];
            float a0v = x0[b*Dq + tid];
            sxv[tid] = make_float2(a0v + tt*(x1[b*Dq+tid]-a0v) + window*dev,
                                   sb[Bq*Dq + b*Dq + tid]);
        }
        __syncthreads();

        u64 zw = pk2(b1[tid], 0.f);
        const u64* sxv64 = (const u64*)sxv;
        #pragma unroll 4
        for (int d = 0; d < Dq; d++) {
            float wv = W1[d*Hq + tid];
            zw = fma2(sxv64[d], pk2(wv,wv), zw);
        }
        float z, w; up2(zw, z, w);
        float th = tanhf(z);
        float s  = 1.f - th*th;
        float u  = -2.f*th*s;
        ss[tid] = s;
        sq[tid] = u*w*w;
        float w2r[Oq];
        #pragma unroll
        for (int o=0;o<Oq;o++) w2r[o] = W2[tid*Oq+o];

        if (tid < 32) {   // ||v||
            float acc = 0.f;
            for (int d = tid; d < Dq; d += 32) { float v = sxv[d].y; acc += v*v; }
            #pragma unroll
            for (int o = 16; o; o >>= 1) acc += __shfl_xor_sync(~0u, acc, o);
            if (tid == 0) g_nv[b] = sqrtf(acc) + 1e-6f;
        }
        __syncthreads();

        // c_o = sum_h W2[h][o] u_h w_h^2   (warp per o)
        int warp = tid>>5, lane = tid&31;
        for (int o = warp; o < Oq; o += 8) {
            float acc = 0.f;
            #pragma unroll
            for (int k = 0; k < 8; k++) { int h = lane + 32*k; acc += W2[h*Oq+o]*sq[h]; }
            #pragma unroll
            for (int off = 16; off; off >>= 1) acc += __shfl_xor_sync(~0u, acc, off);
            if (lane == 0) sc[o] = acc;
        }
        __syncthreads();
        {
            float p = 0.f;
            #pragma unroll
            for (int o=0;o<Oq;o++) p += w2r[o]*sc[o];
            sp[tid] = ss[tid]*p;
        }
        __syncthreads();
        // num_i = sum_g sp_g W1[i][g]  (warp-per-row, 4 concurrent rows)
        for (int r0 = 0; r0 < 16; r0 += 4) {
            int i0 = warp*16 + r0;
            float a0=0.f,a1=0.f,a2=0.f,a3=0.f;
            #pragma unroll
            for (int k = 0; k < 8; k++) {
                int gg = lane + 32*k;
                float spv = sp[gg];
                a0 += spv*W1[(i0+0)*Hq+gg];
                a1 += spv*W1[(i0+1)*Hq+gg];
                a2 += spv*W1[(i0+2)*Hq+gg];
                a3 += spv*W1[(i0+3)*Hq+gg];
            }
            #pragma unroll
            for (int off = 16; off; off >>= 1) {
                a0 += __shfl_xor_sync(~0u,a0,off); a1 += __shfl_xor_sync(~0u,a1,off);
                a2 += __shfl_xor_sync(~0u,a2,off); a3 += __shfl_xor_sync(~0u,a3,off);
            }
            if (lane == 0) {
                g_num[b*Dq+i0+0]=a0; g_num[b*Dq+i0+1]=a1;
                g_num[b*Dq+i0+2]=a2; g_num[b*Dq+i0+3]=a3;
            }
        }
        __threadfence();
        __syncthreads();
        if (tid == 0) strel(&g_pdone[b], 1);
        return;
    }

    // ================= Phase K: 64 blocks (2 per batch, g-halves) =================
    if (bx < BX_Q) {
        int kb = bx - BX_K;
        int b = kb >> 1, half = kb & 1, gbase = half * 128;
        float* sx    = SH;          // [128] x only
        float* ssw2  = SH + 256;    // [256][12]
        float* spart = SH + 3328;   // [256][12] partial K
        float* sKTc  = SH + 6400;   // [128][12] combined K (this g-half)

        float tt = t[0];
        float window = 4.f*tt*(1.f-tt);
        if (tid < Dq) {
            float dev = sb[b*Dq + tid];
            float a0v = x0[b*Dq + tid];
            sx[tid] = a0v + tt*(x1[b*Dq+tid]-a0v) + window*dev;
        }
        __syncthreads();

        float z = b1[tid];
        #pragma unroll 4
        for (int d = 0; d < Dq; d++) z += sx[d]*W1[d*Hq + tid];
        float th = tanhf(z);
        float s  = 1.f - th*th;
        if (half == 0) g_u[b*Hq + tid] = -2.f*th*s;
        #pragma unroll
        for (int o=0;o<Oq;o++) ssw2[tid*12+o] = s*W2[tid*Oq+o];

        if (tid == 0) { while (ldacq(&g_cdone) < NCT) {} }   // wait C (z overlapped it)
        __syncthreads();

        // partial K over an h-half: thread t -> g = gbase+(t&127), h in [hh0,hh0+128)
        {
            int g = gbase + (tid & 127);
            int hh0 = (tid >> 7) * 128;
            u64 k0=0,k1v=0,k2v=0,k3=0,k4=0;
            for (int h = hh0; h < hh0+128; h += 8) {
                float c[8];
                #pragma unroll
                for (int i=0;i<8;i++) c[i] = g_C[(h+i)*Hq + g];
                #pragma unroll
                for (int i=0;i<8;i++) {
                    u64 bb = pk2(c[i],c[i]);
                    const u64* pp = (const u64*)(ssw2 + (h+i)*12);
                    k0=fma2(pp[0],bb,k0); k1v=fma2(pp[1],bb,k1v); k2v=fma2(pp[2],bb,k2v);
                    k3=fma2(pp[3],bb,k3); k4=fma2(pp[4],bb,k4);
                }
            }
            u64* pd = (u64*)(spart + tid*12);
            pd[0]=k0; pd[1]=k1v; pd[2]=k2v; pd[3]=k3; pd[4]=k4;
        }
        __syncthreads();
        if (tid < 128) {   // combine h-halves (fixed order), publish K
            #pragma unroll
            for (int o=0;o<Oq;o++) {
                float kv = spart[tid*12+o] + spart[(tid+128)*12+o];
                sKTc[tid*12+o] = kv;
                g_K[(b*Oq+o)*Hq + gbase + tid] = kv;
            }
        }
        __syncthreads();
        // G2 partial over this g-half
        if (tid < Oq*Oq) {
            int o = tid/Oq, p = tid%Oq;
            float accA = 0.f, accB = 0.f;
            for (int gg = 0; gg < 128; gg += 2) {
                accA += sKTc[gg*12+o]     * ssw2[(gbase+gg)*12+p];
                accB += sKTc[(gg+1)*12+o] * ssw2[(gbase+gg+1)*12+p];
            }
            g_G2p[b][half][tid] = accA + accB;
        }
        __threadfence();
        __syncthreads();
        if (tid == 0) {
            int old = atomicAdd(&g_kcnt[b], 1);
            __threadfence();
            sflag = (old == 1);
            if (old == 1) g_kcnt[b] = 0;   // reset for replay
        }
        __syncthreads();
        if (sflag) {   // second K block: final G2 (fixed order) + release
            if (tid < Oq*Oq)
                g_G2[b*Oq*Oq + tid] = g_G2p[b][0][tid] + g_G2p[b][1][tid];
            __threadfence();
            __syncthreads();
            if (tid == 0) strel(&g_bdone[b], 1);
        }
        return;
    }

    // ================= Phase Q: 256 pair-reduction blocks =================
    {
        int pb = bx - BX_Q;
        int b = pb >> 3, split = pb & (NS-1);
        int h0 = split * 32;
        int g = tid;
        float* sWU  = SH;         // [32][12] W2 row + u_h at [10]
        float* sKTp = SH + 384;   // [32][12]
        float* sG2  = SH + 768;   // [100]

        float w2g[Oq];
        #pragma unroll
        for (int o=0;o<Oq;o++) w2g[o] = W2[g*Oq+o];
        if (split == 0 && tid < Dq)
            out[b*Dq + tid] = sb[Bq*Dq + b*Dq + tid];   // velocity half

        if (tid == 0) { while (ldacq(&g_bdone[b]) == 0) {} }
        __syncthreads();

        if (tid < Oq*Oq) sG2[tid] = g_G2[b*Oq*Oq + tid];
        if (tid >= 128 && tid < 160) {
            int hh = tid - 128, h = h0 + hh;
            #pragma unroll
            for (int o=0;o<Oq;o++){ sWU[hh*12+o]=W2[h*Oq+o]; sKTp[hh*12+o]=g_K[(b*Oq+o)*Hq+h]; }
            sWU[hh*12+10] = g_u[b*Hq+h]; sWU[hh*12+11] = 0.f;
            sKTp[hh*12+10]=0.f; sKTp[hh*12+11]=0.f;
        }
        float u_g = g_u[b*Hq + g];
        float kc[Oq];
        #pragma unroll
        for (int o=0;o<Oq;o++) kc[o] = g_K[(b*Oq+o)*Hq + g];
        __syncthreads();

        float wgs[Oq];
        #pragma unroll
        for (int o=0;o<Oq;o++){
            float a = 0.f;
            #pragma unroll
            for (int p=0;p<Oq;p++) a += sG2[o*Oq+p]*w2g[p];
            wgs[o] = a;
        }
        u64 wgp[5], kcp[5], w2p[5];
        #pragma unroll
        for (int i=0;i<5;i++){ wgp[i]=pk2(wgs[2*i],wgs[2*i+1]); kcp[i]=pk2(kc[2*i],kc[2*i+1]); w2p[i]=pk2(w2g[2*i],w2g[2*i+1]); }

        float acc = 0.f;
        #pragma unroll
        for (int chunk = 0; chunk < 2; chunk++) {
            float c16[16];
            #pragma unroll
            for (int i=0;i<16;i++) c16[i] = g_C[(h0+chunk*16+i)*Hq + g];
            #pragma unroll
            for (int i=0;i<16;i++) {
                int hh = chunk*16 + i;
                const u64* pa  = (const u64*)(sWU  + hh*12);
                const u64* pb2 = (const u64*)(sKTp + hh*12);
                u64 q2=0, r2=0, s2=0;
                #pragma unroll
                for (int j=0;j<5;j++){
                    q2 = fma2(pa[j],  wgp[j], q2);
                    r2 = fma2(pa[j],  kcp[j], r2);
                    s2 = fma2(pb2[j], w2p[j], s2);
                }
                float qq = hadd2(q2), rhg = hadd2(r2), rgh = hadd2(s2);
                float uh = sWU[hh*12+10];
                float cc = c16[i];
                acc += uh*(cc*(cc*qq + rhg*rgh));
            }
        }
        acc *= u_g;
        #pragma unroll
        for (int off = 16; off; off >>= 1) acc += __shfl_xor_sync(~0u, acc, off);
        if ((tid&31) == 0) sred[tid>>5] = acc;
        __syncthreads();
        if (tid == 0) {
            float ttl = 0.f;
            #pragma unroll
            for (int i=0;i<8;i++) ttl += sred[i];
            g_part[b*NS + split] = ttl;
            __threadfence();
            int old = atomicAdd(&g_cnt[b], 1);
            sflag = (old == NS-1);
        }
        __syncthreads();
        if (sflag) {   // per-batch finalize (fixed-order sums — deterministic)
            if (tid == 0) {
                while (ldacq(&g_pdone[b]) == 0) {}
                __threadfence();
                float n2 = 0.f;
                #pragma unroll
                for (int k=0;k<NS;k++) n2 += g_part[b*NS + k];
                n2 *= 2.f;
                float nF = sqrtf(fmaxf(n2, 0.f)) + 1e-6f;
                sscale = -1.f/(nF * g_nv[b]);
                g_cnt[b] = 0;   // reset for replay
            }
            __syncthreads();
            if (tid < Dq)
                out[Bq*Dq + b*Dq + tid] = g_num[b*Dq+tid]*sscale - 0.1f*sb[b*Dq+tid];
        }
        if (tid == 0) {   // global epilogue: last pair block resets flags for replay
            int old = atomicAdd(&g_all, 1);
            if (old == NP-1) {
                g_cdone = 0;
                #pragma unroll
                for (int i=0;i<Bq;i++) { g_bdone[i] = 0; g_pdone[i] = 0; }
                g_all = 0;
            }
        }
    }
}

extern "C" void kernel_launch(void* const* d_in, const int* in_sizes, int n_in,
                              void* d_out, int out_size) {
    const float* t  = (const float*)d_in[0];
    const float* sb = (const float*)d_in[1];
    const float* x0 = (const float*)d_in[2];
    const float* x1 = (const float*)d_in[3];
    const float* W1 = (const float*)d_in[4];
    const float* b1 = (const float*)d_in[5];
    const float* W2 = (const float*)d_in[6];
    float* out = (float*)d_out;

    mega<<<GRID, 256>>>(t, sb, x0, x1, W1, b1, W2, out);
}

// round 5
// speedup vs baseline: 2.4694x; 1.3151x over previous
#include <cuda_runtime.h>
#include <math.h>

typedef unsigned long long u64;
#define Bq 32
#define Dq 128
#define Hq 256
#define Oq 10
#define NCT 36                // C tile blocks (upper-tri of 8x8 tiles of 32)
#define NKB 4                 // K blocks per batch (g-quarters)
#define NS  8                 // h-splits per batch in pair phase
#define NP  (Bq*NS)           // 256 pair blocks
#define BX_P (NCT)            // 36  : P blocks start
#define BX_K (NCT+Bq)         // 68  : K blocks start
#define BX_Q (BX_K+NKB*Bq)    // 196 : pair blocks start
#define GRID (BX_Q+NP)        // 452 total (< 592 resident capacity -> 1 wave)

// Scratch (allocation-free rule: __device__ globals; zero-initialized)
__device__ float g_C[Hq*Hq];
__device__ float g_K[Bq*Oq*Hq];
__device__ float g_u[Bq*Hq];
__device__ float g_G2p[Bq][NKB][112];
__device__ float g_G2[Bq*Oq*Oq];
__device__ float g_num[Bq*Dq];
__device__ float g_nv[Bq];
__device__ float g_part[Bq*NS];
__device__ int   g_cdone;
__device__ int   g_kcnt[Bq];
__device__ int   g_bdone[Bq];
__device__ int   g_pdone[Bq];
__device__ int   g_cnt[Bq];
__device__ int   g_all;

// ---- f32x2 packed helpers (sm_103a) ----
__device__ __forceinline__ u64 pk2(float x, float y){ u64 r; asm("mov.b64 %0,{%1,%2};" : "=l"(r) : "f"(x),"f"(y)); return r; }
__device__ __forceinline__ u64 fma2(u64 a,u64 b,u64 c){ u64 d; asm("fma.rn.f32x2 %0,%1,%2,%3;" : "=l"(d) : "l"(a),"l"(b),"l"(c)); return d; }
__device__ __forceinline__ void up2(u64 a, float&x, float&y){ asm("mov.b64 {%0,%1},%2;" : "=f"(x),"=f"(y) : "l"(a)); }
__device__ __forceinline__ float hadd2(u64 a){ float x,y; up2(a,x,y); return x+y; }
__device__ __forceinline__ int ldacq(const int* p){
    int v; asm volatile("ld.global.acquire.gpu.b32 %0, [%1];" : "=r"(v) : "l"(p) : "memory"); return v;
}
__device__ __forceinline__ void strel(int* p, int v){
    asm volatile("st.global.release.gpu.b32 [%0], %1;" :: "l"(p), "r"(v) : "memory");
}

__global__ void __launch_bounds__(256, 4)
mega(const float* __restrict__ t,  const float* __restrict__ sb,
     const float* __restrict__ x0, const float* __restrict__ x1,
     const float* __restrict__ W1, const float* __restrict__ b1,
     const float* __restrict__ W2, float* __restrict__ out)
{
    __shared__ __align__(16) float SH[9600];
    __shared__ float sred[8];
    __shared__ float sscale;
    __shared__ int   sflag;
    int tid = threadIdx.x;
    int bx  = blockIdx.x;

    // ================= Phase C: C = W1^T W1 (36 symmetric tiles) =================
    if (bx < NCT) {
        int r = bx, ti = 0;
        while (r >= 8 - ti) { r -= 8 - ti; ti++; }
        int tj = ti + r;
        float* shA = SH;            // [128][36]
        float* shB = SH + 4608;     // [128][36]
        for (int i = tid; i < 4096; i += 256) {
            int d = i >> 5, col = i & 31;
            shA[d*36+col] = W1[d*Hq + ti*32 + col];
            shB[d*36+col] = W1[d*Hq + tj*32 + col];
        }
        __syncthreads();
        int jb = tid & 31, a0 = (tid >> 5) * 4;
        float acc0=0.f, acc1=0.f, acc2=0.f, acc3=0.f;
        #pragma unroll 4
        for (int d = 0; d < Dq; d++) {
            float4 av = *(const float4*)(shA + d*36 + a0);
            float  bv = shB[d*36 + jb];
            acc0 += av.x*bv; acc1 += av.y*bv; acc2 += av.z*bv; acc3 += av.w*bv;
        }
        int h0 = ti*32, g0 = tj*32;
        g_C[(h0+a0+0)*Hq + g0+jb] = acc0;
        g_C[(h0+a0+1)*Hq + g0+jb] = acc1;
        g_C[(h0+a0+2)*Hq + g0+jb] = acc2;
        g_C[(h0+a0+3)*Hq + g0+jb] = acc3;
        if (ti != tj) {
            g_C[(g0+jb)*Hq + h0+a0+0] = acc0;
            g_C[(g0+jb)*Hq + h0+a0+1] = acc1;
            g_C[(g0+jb)*Hq + h0+a0+2] = acc2;
            g_C[(g0+jb)*Hq + h0+a0+3] = acc3;
        }
        __threadfence();
        __syncthreads();
        if (tid == 0) atomicAdd(&g_cdone, 1);
        return;
    }

    // ================= Phase P: 32 C-free per-batch blocks (overlaps C) =================
    if (bx < BX_K) {
        int b = bx - BX_P;
        float2* sxv = (float2*)SH;        // [128] (x,v)
        float*  ss  = SH + 256;
        float*  sq  = SH + 512;           // u*w^2
        float*  sp  = SH + 768;
        float*  sc  = SH + 1024;          // [16]

        float tt = t[0];
        float window = 4.f*tt*(1.f-tt);
        if (tid < Dq) {
            float dev = sb[b*Dq + tid];
            float a0v = x0[b*Dq + tid];
            sxv[tid] = make_float2(a0v + tt*(x1[b*Dq+tid]-a0v) + window*dev,
                                   sb[Bq*Dq + b*Dq + tid]);
        }
        __syncthreads();

        u64 zw = pk2(b1[tid], 0.f);
        const u64* sxv64 = (const u64*)sxv;
        #pragma unroll 4
        for (int d = 0; d < Dq; d++) {
            float wv = W1[d*Hq + tid];
            zw = fma2(sxv64[d], pk2(wv,wv), zw);
        }
        float z, w; up2(zw, z, w);
        float th = tanhf(z);
        float s  = 1.f - th*th;
        float u  = -2.f*th*s;
        ss[tid] = s;
        sq[tid] = u*w*w;
        float w2r[Oq];
        #pragma unroll
        for (int o=0;o<Oq;o++) w2r[o] = W2[tid*Oq+o];

        if (tid < 32) {   // ||v||
            float acc = 0.f;
            for (int d = tid; d < Dq; d += 32) { float v = sxv[d].y; acc += v*v; }
            #pragma unroll
            for (int o = 16; o; o >>= 1) acc += __shfl_xor_sync(~0u, acc, o);
            if (tid == 0) g_nv[b] = sqrtf(acc) + 1e-6f;
        }
        __syncthreads();

        // c_o = sum_h W2[h][o] u_h w_h^2   (warp per o)
        int warp = tid>>5, lane = tid&31;
        for (int o = warp; o < Oq; o += 8) {
            float acc = 0.f;
            #pragma unroll
            for (int k = 0; k < 8; k++) { int h = lane + 32*k; acc += W2[h*Oq+o]*sq[h]; }
            #pragma unroll
            for (int off = 16; off; off >>= 1) acc += __shfl_xor_sync(~0u, acc, off);
            if (lane == 0) sc[o] = acc;
        }
        __syncthreads();
        {
            float p = 0.f;
            #pragma unroll
            for (int o=0;o<Oq;o++) p += w2r[o]*sc[o];
            sp[tid] = ss[tid]*p;
        }
        __syncthreads();
        // num_i = sum_g sp_g W1[i][g]  (warp-per-row, 4 concurrent rows)
        for (int r0 = 0; r0 < 16; r0 += 4) {
            int i0 = warp*16 + r0;
            float a0=0.f,a1=0.f,a2=0.f,a3=0.f;
            #pragma unroll
            for (int k = 0; k < 8; k++) {
                int gg = lane + 32*k;
                float spv = sp[gg];
                a0 += spv*W1[(i0+0)*Hq+gg];
                a1 += spv*W1[(i0+1)*Hq+gg];
                a2 += spv*W1[(i0+2)*Hq+gg];
                a3 += spv*W1[(i0+3)*Hq+gg];
            }
            #pragma unroll
            for (int off = 16; off; off >>= 1) {
                a0 += __shfl_xor_sync(~0u,a0,off); a1 += __shfl_xor_sync(~0u,a1,off);
                a2 += __shfl_xor_sync(~0u,a2,off); a3 += __shfl_xor_sync(~0u,a3,off);
            }
            if (lane == 0) {
                g_num[b*Dq+i0+0]=a0; g_num[b*Dq+i0+1]=a1;
                g_num[b*Dq+i0+2]=a2; g_num[b*Dq+i0+3]=a3;
            }
        }
        __threadfence();
        __syncthreads();
        if (tid == 0) strel(&g_pdone[b], 1);
        return;
    }

    // ================= Phase K: 128 blocks (4 per batch, g-quarters) =================
    if (bx < BX_Q) {
        int kb = bx - BX_K;
        int b = kb >> 2, quarter = kb & 3, gbase = quarter * 64;
        float* sx    = SH;          // [128]
        float* ssw2  = SH + 256;    // [256][12]
        float* spart = SH + 3328;   // [256][12] partial K (g-local x h-quarter)
        float* sKTc  = SH + 6400;   // [64][12] combined K (this g-quarter)

        float tt = t[0];
        float window = 4.f*tt*(1.f-tt);
        if (tid < Dq) {
            float dev = sb[b*Dq + tid];
            float a0v = x0[b*Dq + tid];
            sx[tid] = a0v + tt*(x1[b*Dq+tid]-a0v) + window*dev;
        }
        __syncthreads();

        float z = b1[tid];
        #pragma unroll 4
        for (int d = 0; d < Dq; d++) z += sx[d]*W1[d*Hq + tid];
        float th = tanhf(z);
        float s  = 1.f - th*th;
        if (quarter == 0) g_u[b*Hq + tid] = -2.f*th*s;
        #pragma unroll
        for (int o=0;o<Oq;o++) ssw2[tid*12+o] = s*W2[tid*Oq+o];

        if (tid == 0) { while (ldacq(&g_cdone) < NCT) {} }   // wait C (z overlapped it)
        __syncthreads();

        // partial K: thread -> g = gbase+(tid&63), h in [hbase,hbase+64), double-buffered
        {
            int g = gbase + (tid & 63);
            int hbase = (tid >> 6) * 64;
            float cb[2][16];
            #pragma unroll
            for (int i=0;i<16;i++) cb[0][i] = g_C[(hbase+i)*Hq + g];
            u64 k0=0,k1v=0,k2v=0,k3=0,k4=0;
            #pragma unroll
            for (int ch = 0; ch < 4; ch++) {
                int cur = ch & 1;
                if (ch < 3) {
                    #pragma unroll
                    for (int i=0;i<16;i++) cb[cur^1][i] = g_C[(hbase+(ch+1)*16+i)*Hq + g];
                }
                #pragma unroll
                for (int i=0;i<16;i++) {
                    float c = cb[cur][i];
                    u64 bb = pk2(c,c);
                    const u64* pp = (const u64*)(ssw2 + (hbase+ch*16+i)*12);
                    k0=fma2(pp[0],bb,k0); k1v=fma2(pp[1],bb,k1v); k2v=fma2(pp[2],bb,k2v);
                    k3=fma2(pp[3],bb,k3); k4=fma2(pp[4],bb,k4);
                }
            }
            u64* pd = (u64*)(spart + tid*12);
            pd[0]=k0; pd[1]=k1v; pd[2]=k2v; pd[3]=k3; pd[4]=k4;
        }
        __syncthreads();
        if (tid < 64) {   // combine 4 h-quarters (fixed order), publish K
            #pragma unroll
            for (int o=0;o<Oq;o++) {
                float kv = spart[tid*12+o] + spart[(tid+64)*12+o]
                         + spart[(tid+128)*12+o] + spart[(tid+192)*12+o];
                sKTc[tid*12+o] = kv;
                g_K[(b*Oq+o)*Hq + gbase + tid] = kv;
            }
        }
        __syncthreads();
        // G2 partial over this g-quarter (chain length 64, 2 accumulators)
        if (tid < Oq*Oq) {
            int o = tid/Oq, p = tid%Oq;
            float accA = 0.f, accB = 0.f;
            #pragma unroll 4
            for (int gg = 0; gg < 64; gg += 2) {
                accA += sKTc[gg*12+o]     * ssw2[(gbase+gg)*12+p];
                accB += sKTc[(gg+1)*12+o] * ssw2[(gbase+gg+1)*12+p];
            }
            g_G2p[b][quarter][tid] = accA + accB;
        }
        __threadfence();
        __syncthreads();
        if (tid == 0) {
            int old = atomicAdd(&g_kcnt[b], 1);
            __threadfence();
            sflag = (old == NKB-1);
            if (old == NKB-1) g_kcnt[b] = 0;   // reset for replay
        }
        __syncthreads();
        if (sflag) {   // last K block: final G2 (fixed order) + release
            if (tid < Oq*Oq)
                g_G2[b*Oq*Oq + tid] = g_G2p[b][0][tid] + g_G2p[b][1][tid]
                                    + g_G2p[b][2][tid] + g_G2p[b][3][tid];
            __threadfence();
            __syncthreads();
            if (tid == 0) strel(&g_bdone[b], 1);
        }
        return;
    }

    // ================= Phase Q: 256 pair-reduction blocks =================
    {
        int pb = bx - BX_Q;
        int b = pb >> 3, split = pb & (NS-1);
        int h0 = split * 32;
        int g = tid;
        float* sWU  = SH;         // [32][12] W2 row + u_h at [10]
        float* sKTp = SH + 384;   // [32][12]
        float* sG2  = SH + 768;   // [100]

        float w2g[Oq];
        #pragma unroll
        for (int o=0;o<Oq;o++) w2g[o] = W2[g*Oq+o];
        if (split == 0 && tid < Dq)
            out[b*Dq + tid] = sb[Bq*Dq + b*Dq + tid];   // velocity half

        if (tid == 0) { while (ldacq(&g_bdone[b]) == 0) {} }
        __syncthreads();

        if (tid < Oq*Oq) sG2[tid] = g_G2[b*Oq*Oq + tid];
        if (tid >= 128 && tid < 160) {
            int hh = tid - 128, h = h0 + hh;
            #pragma unroll
            for (int o=0;o<Oq;o++){ sWU[hh*12+o]=W2[h*Oq+o]; sKTp[hh*12+o]=g_K[(b*Oq+o)*Hq+h]; }
            sWU[hh*12+10] = g_u[b*Hq+h]; sWU[hh*12+11] = 0.f;
            sKTp[hh*12+10]=0.f; sKTp[hh*12+11]=0.f;
        }
        float u_g = g_u[b*Hq + g];
        float kc[Oq];
        #pragma unroll
        for (int o=0;o<Oq;o++) kc[o] = g_K[(b*Oq+o)*Hq + g];
        __syncthreads();

        float wgs[Oq];
        #pragma unroll
        for (int o=0;o<Oq;o++){
            float a = 0.f;
            #pragma unroll
            for (int p=0;p<Oq;p++) a += sG2[o*Oq+p]*w2g[p];
            wgs[o] = a;
        }
        u64 wgp[5], kcp[5], w2p[5];
        #pragma unroll
        for (int i=0;i<5;i++){ wgp[i]=pk2(wgs[2*i],wgs[2*i+1]); kcp[i]=pk2(kc[2*i],kc[2*i+1]); w2p[i]=pk2(w2g[2*i],w2g[2*i+1]); }

        float acc = 0.f;
        #pragma unroll
        for (int chunk = 0; chunk < 2; chunk++) {
            float c16[16];
            #pragma unroll
            for (int i=0;i<16;i++) c16[i] = g_C[(h0+chunk*16+i)*Hq + g];
            #pragma unroll
            for (int i=0;i<16;i++) {
                int hh = chunk*16 + i;
                const u64* pa  = (const u64*)(sWU  + hh*12);
                const u64* pb2 = (const u64*)(sKTp + hh*12);
                u64 q2=0, r2=0, s2=0;
                #pragma unroll
                for (int j=0;j<5;j++){
                    q2 = fma2(pa[j],  wgp[j], q2);
                    r2 = fma2(pa[j],  kcp[j], r2);
                    s2 = fma2(pb2[j], w2p[j], s2);
                }
                float qq = hadd2(q2), rhg = hadd2(r2), rgh = hadd2(s2);
                float uh = sWU[hh*12+10];
                float cc = c16[i];
                acc += uh*(cc*(cc*qq + rhg*rgh));
            }
        }
        acc *= u_g;
        #pragma unroll
        for (int off = 16; off; off >>= 1) acc += __shfl_xor_sync(~0u, acc, off);
        if ((tid&31) == 0) sred[tid>>5] = acc;
        __syncthreads();
        if (tid == 0) {
            float ttl = 0.f;
            #pragma unroll
            for (int i=0;i<8;i++) ttl += sred[i];
            g_part[b*NS + split] = ttl;
            __threadfence();
            int old = atomicAdd(&g_cnt[b], 1);
            sflag = (old == NS-1);
        }
        __syncthreads();
        if (sflag) {   // per-batch finalize (fixed-order sums — deterministic)
            if (tid == 0) {
                while (ldacq(&g_pdone[b]) == 0) {}
                __threadfence();
                float n2 = 0.f;
                #pragma unroll
                for (int k=0;k<NS;k++) n2 += g_part[b*NS + k];
                n2 *= 2.f;
                float nF = sqrtf(fmaxf(n2, 0.f)) + 1e-6f;
                sscale = -1.f/(nF * g_nv[b]);
                g_cnt[b] = 0;   // reset for replay
            }
            __syncthreads();
            if (tid < Dq)
                out[Bq*Dq + b*Dq + tid] = g_num[b*Dq+tid]*sscale - 0.1f*sb[b*Dq+tid];
        }
        if (tid == 0) {   // global epilogue: last pair block resets flags for replay
            int old = atomicAdd(&g_all, 1);
            if (old == NP-1) {
                g_cdone = 0;
                #pragma unroll
                for (int i=0;i<Bq;i++) { g_bdone[i] = 0; g_pdone[i] = 0; }
                g_all = 0;
            }
        }
    }
}

extern "C" void kernel_launch(void* const* d_in, const int* in_sizes, int n_in,
                              void* d_out, int out_size) {
    const float* t  = (const float*)d_in[0];
    const float* sb = (const float*)d_in[1];
    const float* x0 = (const float*)d_in[2];
    const float* x1 = (const float*)d_in[3];
    const float* W1 = (const float*)d_in[4];
    const float* b1 = (const float*)d_in[5];
    const float* W2 = (const float*)d_in[6];
    float* out = (float*)d_out;

    mega<<<GRID, 256>>>(t, sb, x0, x1, W1, b1, W2, out);
}

// round 6
// speedup vs baseline: 2.4725x; 1.0013x over previous
#include <cuda_runtime.h>
#include <math.h>

typedef unsigned long long u64;
#define Bq 32
#define Dq 128
#define Hq 256
#define Oq 10
#define NCT 36                // C tile blocks (upper-tri of 8x8 tiles of 32)
#define NKB 4                 // K blocks per batch (g-quarters)
#define NS  8                 // h-splits per batch in pair phase
#define NP  (Bq*NS)           // 256 pair blocks
#define BX_P (NCT)            // 36  : P blocks start
#define BX_K (NCT+Bq)         // 68  : K blocks start
#define BX_Q (BX_K+NKB*Bq)    // 196 : pair blocks start
#define GRID (BX_Q+NP)        // 452 total (< 592 resident capacity -> 1 wave)

// Scratch (allocation-free rule: __device__ globals; zero-initialized)
__device__ float g_C[Hq*Hq];
__device__ float g_K[Bq*Oq*Hq];
__device__ float g_u[Bq*Hq];
__device__ float g_G2p[Bq][NKB][112];
__device__ float g_G2[Bq*Oq*Oq];
__device__ float g_num[Bq*Dq];
__device__ float g_nv[Bq];
__device__ float g_part[Bq*NS];
__device__ int   g_cdone;
__device__ int   g_kcnt[Bq];
__device__ int   g_bdone[Bq];
__device__ int   g_pdone[Bq];
__device__ int   g_cnt[Bq];
__device__ int   g_all;

// ---- f32x2 packed helpers (sm_103a) ----
__device__ __forceinline__ u64 pk2(float x, float y){ u64 r; asm("mov.b64 %0,{%1,%2};" : "=l"(r) : "f"(x),"f"(y)); return r; }
__device__ __forceinline__ u64 fma2(u64 a,u64 b,u64 c){ u64 d; asm("fma.rn.f32x2 %0,%1,%2,%3;" : "=l"(d) : "l"(a),"l"(b),"l"(c)); return d; }
__device__ __forceinline__ void up2(u64 a, float&x, float&y){ asm("mov.b64 {%0,%1},%2;" : "=f"(x),"=f"(y) : "l"(a)); }
__device__ __forceinline__ float hadd2(u64 a){ float x,y; up2(a,x,y); return x+y; }
__device__ __forceinline__ int ldacq(const int* p){
    int v; asm volatile("ld.global.acquire.gpu.b32 %0, [%1];" : "=r"(v) : "l"(p) : "memory"); return v;
}
__device__ __forceinline__ void strel(int* p, int v){
    asm volatile("st.global.release.gpu.b32 [%0], %1;" :: "l"(p), "r"(v) : "memory");
}

__global__ void __launch_bounds__(256, 4)
mega(const float* __restrict__ t,  const float* __restrict__ sb,
     const float* __restrict__ x0, const float* __restrict__ x1,
     const float* __restrict__ W1, const float* __restrict__ b1,
     const float* __restrict__ W2, float* __restrict__ out)
{
    __shared__ __align__(16) float SH[9600];
    __shared__ float sred[8];
    __shared__ float sscale;
    __shared__ int   sflag;
    int tid = threadIdx.x;
    int bx  = blockIdx.x;

    // ================= Phase C: C = W1^T W1 (36 symmetric tiles) =================
    if (bx < NCT) {
        int r = bx, ti = 0;
        while (r >= 8 - ti) { r -= 8 - ti; ti++; }
        int tj = ti + r;
        float* shA = SH;            // [128][36]
        float* shB = SH + 4608;     // [128][36]
        for (int i = tid; i < 4096; i += 256) {
            int d = i >> 5, col = i & 31;
            shA[d*36+col] = W1[d*Hq + ti*32 + col];
            shB[d*36+col] = W1[d*Hq + tj*32 + col];
        }
        __syncthreads();
        int jb = tid & 31, a0 = (tid >> 5) * 4;
        float acc0=0.f, acc1=0.f, acc2=0.f, acc3=0.f;
        #pragma unroll 4
        for (int d = 0; d < Dq; d++) {
            float4 av = *(const float4*)(shA + d*36 + a0);
            float  bv = shB[d*36 + jb];
            acc0 += av.x*bv; acc1 += av.y*bv; acc2 += av.z*bv; acc3 += av.w*bv;
        }
        int h0 = ti*32, g0 = tj*32;
        g_C[(h0+a0+0)*Hq + g0+jb] = acc0;
        g_C[(h0+a0+1)*Hq + g0+jb] = acc1;
        g_C[(h0+a0+2)*Hq + g0+jb] = acc2;
        g_C[(h0+a0+3)*Hq + g0+jb] = acc3;
        if (ti != tj) {
            g_C[(g0+jb)*Hq + h0+a0+0] = acc0;
            g_C[(g0+jb)*Hq + h0+a0+1] = acc1;
            g_C[(g0+jb)*Hq + h0+a0+2] = acc2;
            g_C[(g0+jb)*Hq + h0+a0+3] = acc3;
        }
        __threadfence();
        __syncthreads();
        if (tid == 0) atomicAdd(&g_cdone, 1);
        return;
    }

    // ================= Phase P: 32 C-free per-batch blocks (overlaps C) =================
    if (bx < BX_K) {
        int b = bx - BX_P;
        float2* sxv = (float2*)SH;        // [128] (x,v)
        float*  ss  = SH + 256;
        float*  sq  = SH + 512;           // u*w^2
        float*  sp  = SH + 768;
        float*  sc  = SH + 1024;          // [16]

        float tt = t[0];
        float window = 4.f*tt*(1.f-tt);
        if (tid < Dq) {
            float dev = sb[b*Dq + tid];
            float a0v = x0[b*Dq + tid];
            sxv[tid] = make_float2(a0v + tt*(x1[b*Dq+tid]-a0v) + window*dev,
                                   sb[Bq*Dq + b*Dq + tid]);
        }
        __syncthreads();

        u64 zw = pk2(b1[tid], 0.f);
        const u64* sxv64 = (const u64*)sxv;
        #pragma unroll 4
        for (int d = 0; d < Dq; d++) {
            float wv = W1[d*Hq + tid];
            zw = fma2(sxv64[d], pk2(wv,wv), zw);
        }
        float z, w; up2(zw, z, w);
        float th = tanhf(z);
        float s  = 1.f - th*th;
        float u  = -2.f*th*s;
        ss[tid] = s;
        sq[tid] = u*w*w;
        float w2r[Oq];
        #pragma unroll
        for (int o=0;o<Oq;o++) w2r[o] = W2[tid*Oq+o];

        if (tid < 32) {   // ||v||
            float acc = 0.f;
            for (int d = tid; d < Dq; d += 32) { float v = sxv[d].y; acc += v*v; }
            #pragma unroll
            for (int o = 16; o; o >>= 1) acc += __shfl_xor_sync(~0u, acc, o);
            if (tid == 0) g_nv[b] = sqrtf(acc) + 1e-6f;
        }
        __syncthreads();

        // c_o = sum_h W2[h][o] u_h w_h^2   (warp per o)
        int warp = tid>>5, lane = tid&31;
        for (int o = warp; o < Oq; o += 8) {
            float acc = 0.f;
            #pragma unroll
            for (int k = 0; k < 8; k++) { int h = lane + 32*k; acc += W2[h*Oq+o]*sq[h]; }
            #pragma unroll
            for (int off = 16; off; off >>= 1) acc += __shfl_xor_sync(~0u, acc, off);
            if (lane == 0) sc[o] = acc;
        }
        __syncthreads();
        {
            float p = 0.f;
            #pragma unroll
            for (int o=0;o<Oq;o++) p += w2r[o]*sc[o];
            sp[tid] = ss[tid]*p;
        }
        __syncthreads();
        // num_i = sum_g sp_g W1[i][g]  (warp-per-row, 4 concurrent rows)
        for (int r0 = 0; r0 < 16; r0 += 4) {
            int i0 = warp*16 + r0;
            float a0=0.f,a1=0.f,a2=0.f,a3=0.f;
            #pragma unroll
            for (int k = 0; k < 8; k++) {
                int gg = lane + 32*k;
                float spv = sp[gg];
                a0 += spv*W1[(i0+0)*Hq+gg];
                a1 += spv*W1[(i0+1)*Hq+gg];
                a2 += spv*W1[(i0+2)*Hq+gg];
                a3 += spv*W1[(i0+3)*Hq+gg];
            }
            #pragma unroll
            for (int off = 16; off; off >>= 1) {
                a0 += __shfl_xor_sync(~0u,a0,off); a1 += __shfl_xor_sync(~0u,a1,off);
                a2 += __shfl_xor_sync(~0u,a2,off); a3 += __shfl_xor_sync(~0u,a3,off);
            }
            if (lane == 0) {
                g_num[b*Dq+i0+0]=a0; g_num[b*Dq+i0+1]=a1;
                g_num[b*Dq+i0+2]=a2; g_num[b*Dq+i0+3]=a3;
            }
        }
        __threadfence();
        __syncthreads();
        if (tid == 0) strel(&g_pdone[b], 1);
        return;
    }

    // ================= Phase K: 128 blocks (4 per batch, g-quarters) =================
    if (bx < BX_Q) {
        int kb = bx - BX_K;
        int b = kb >> 2, quarter = kb & 3, gbase = quarter * 64;
        float* sx    = SH;          // [128]
        float* ssw2  = SH + 256;    // [256][12]
        float* spart = SH + 3328;   // [256][12] partial K (g-local x h-quarter)
        float* sKTc  = SH + 6400;   // [64][12] combined K (this g-quarter)

        float tt = t[0];
        float window = 4.f*tt*(1.f-tt);
        if (tid < Dq) {
            float dev = sb[b*Dq + tid];
            float a0v = x0[b*Dq + tid];
            sx[tid] = a0v + tt*(x1[b*Dq+tid]-a0v) + window*dev;
        }
        __syncthreads();

        // z with 4 independent accumulator chains (MLP~16)
        float z0 = b1[tid], z1 = 0.f, z2 = 0.f, z3 = 0.f;
        #pragma unroll 4
        for (int d = 0; d < Dq; d += 4) {
            z0 += sx[d+0]*W1[(d+0)*Hq + tid];
            z1 += sx[d+1]*W1[(d+1)*Hq + tid];
            z2 += sx[d+2]*W1[(d+2)*Hq + tid];
            z3 += sx[d+3]*W1[(d+3)*Hq + tid];
        }
        float z = (z0+z1)+(z2+z3);
        float th = tanhf(z);
        float s  = 1.f - th*th;
        if (quarter == 0) g_u[b*Hq + tid] = -2.f*th*s;
        #pragma unroll
        for (int o=0;o<Oq;o++) ssw2[tid*12+o] = s*W2[tid*Oq+o];

        if (tid == 0) { while (ldacq(&g_cdone) < NCT) {} }   // wait C (z overlapped it)
        __syncthreads();

        // partial K: thread -> g = gbase+(tid&63), h in [hbase,hbase+64), double-buffered
        {
            int g = gbase + (tid & 63);
            int hbase = (tid >> 6) * 64;
            float cb[2][16];
            #pragma unroll
            for (int i=0;i<16;i++) cb[0][i] = g_C[(hbase+i)*Hq + g];
            u64 k0=0,k1v=0,k2v=0,k3=0,k4=0;
            #pragma unroll
            for (int ch = 0; ch < 4; ch++) {
                int cur = ch & 1;
                if (ch < 3) {
                    #pragma unroll
                    for (int i=0;i<16;i++) cb[cur^1][i] = g_C[(hbase+(ch+1)*16+i)*Hq + g];
                }
                #pragma unroll
                for (int i=0;i<16;i++) {
                    float c = cb[cur][i];
                    u64 bb = pk2(c,c);
                    const u64* pp = (const u64*)(ssw2 + (hbase+ch*16+i)*12);
                    k0=fma2(pp[0],bb,k0); k1v=fma2(pp[1],bb,k1v); k2v=fma2(pp[2],bb,k2v);
                    k3=fma2(pp[3],bb,k3); k4=fma2(pp[4],bb,k4);
                }
            }
            u64* pd = (u64*)(spart + tid*12);
            pd[0]=k0; pd[1]=k1v; pd[2]=k2v; pd[3]=k3; pd[4]=k4;
        }
        __syncthreads();
        if (tid < 64) {   // combine 4 h-quarters (fixed order), publish K
            #pragma unroll
            for (int o=0;o<Oq;o++) {
                float kv = spart[tid*12+o] + spart[(tid+64)*12+o]
                         + spart[(tid+128)*12+o] + spart[(tid+192)*12+o];
                sKTc[tid*12+o] = kv;
                g_K[(b*Oq+o)*Hq + gbase + tid] = kv;
            }
        }
        __syncthreads();
        // G2 partial over this g-quarter (chain length 64, 2 accumulators)
        if (tid < Oq*Oq) {
            int o = tid/Oq, p = tid%Oq;
            float accA = 0.f, accB = 0.f;
            #pragma unroll 4
            for (int gg = 0; gg < 64; gg += 2) {
                accA += sKTc[gg*12+o]     * ssw2[(gbase+gg)*12+p];
                accB += sKTc[(gg+1)*12+o] * ssw2[(gbase+gg+1)*12+p];
            }
            g_G2p[b][quarter][tid] = accA + accB;
        }
        __threadfence();
        __syncthreads();
        if (tid == 0) {
            int old = atomicAdd(&g_kcnt[b], 1);
            __threadfence();
            sflag = (old == NKB-1);
            if (old == NKB-1) g_kcnt[b] = 0;   // reset for replay
        }
        __syncthreads();
        if (sflag) {   // last K block: final G2 (fixed order) + release
            if (tid < Oq*Oq)
                g_G2[b*Oq*Oq + tid] = g_G2p[b][0][tid] + g_G2p[b][1][tid]
                                    + g_G2p[b][2][tid] + g_G2p[b][3][tid];
            __threadfence();
            __syncthreads();
            if (tid == 0) strel(&g_bdone[b], 1);
        }
        return;
    }

    // ===== Phase Q: 256 pair blocks, SYMMETRY-HALVED (upper tiles x2, diag x1) =====
    {
        int pb = bx - BX_Q;
        int b = pb >> 3, split = pb & (NS-1);
        int h0 = split * 32;
        int g = tid;
        float* sWU  = SH;         // [32][12] W2 row + u_h at [10]
        float* sKTp = SH + 384;   // [32][12]
        float* sG2  = SH + 768;   // [100]

        bool active = (g >= h0);  // warp-uniform (h0 multiple of 32)

        if (split == 0 && tid < Dq)
            out[b*Dq + tid] = sb[Bq*Dq + b*Dq + tid];   // velocity half

        if (tid == 0) { while (ldacq(&g_bdone[b]) == 0) {} }
        __syncthreads();

        if (tid < Oq*Oq) sG2[tid] = g_G2[b*Oq*Oq + tid];
        if (tid >= 128 && tid < 160) {
            int hh = tid - 128, h = h0 + hh;
            #pragma unroll
            for (int o=0;o<Oq;o++){ sWU[hh*12+o]=W2[h*Oq+o]; sKTp[hh*12+o]=g_K[(b*Oq+o)*Hq+h]; }
            sWU[hh*12+10] = g_u[b*Hq+h]; sWU[hh*12+11] = 0.f;
            sKTp[hh*12+10]=0.f; sKTp[hh*12+11]=0.f;
        }
        __syncthreads();

        float acc = 0.f;
        if (active) {
            float u_g = g_u[b*Hq + g];
            float w2g[Oq], kc[Oq];
            #pragma unroll
            for (int o=0;o<Oq;o++){ w2g[o] = W2[g*Oq+o]; kc[o] = g_K[(b*Oq+o)*Hq + g]; }

            float wgs[Oq];
            #pragma unroll
            for (int o=0;o<Oq;o++){
                float a = 0.f;
                #pragma unroll
                for (int p=0;p<Oq;p++) a += sG2[o*Oq+p]*w2g[p];
                wgs[o] = a;
            }
            u64 wgp[5], kcp[5], w2p[5];
            #pragma unroll
            for (int i=0;i<5;i++){ wgp[i]=pk2(wgs[2*i],wgs[2*i+1]); kcp[i]=pk2(kc[2*i],kc[2*i+1]); w2p[i]=pk2(w2g[2*i],w2g[2*i+1]); }

            #pragma unroll
            for (int chunk = 0; chunk < 2; chunk++) {
                float c16[16];
                #pragma unroll
                for (int i=0;i<16;i++) c16[i] = g_C[(h0+chunk*16+i)*Hq + g];
                #pragma unroll
                for (int i=0;i<16;i++) {
                    int hh = chunk*16 + i;
                    const u64* pa  = (const u64*)(sWU  + hh*12);
                    const u64* pb2 = (const u64*)(sKTp + hh*12);
                    u64 q2=0, r2=0, s2=0;
                    #pragma unroll
                    for (int j=0;j<5;j++){
                        q2 = fma2(pa[j],  wgp[j], q2);
                        r2 = fma2(pa[j],  kcp[j], r2);
                        s2 = fma2(pb2[j], w2p[j], s2);
                    }
                    float qq = hadd2(q2), rhg = hadd2(r2), rgh = hadd2(s2);
                    float uh = sWU[hh*12+10];
                    float cc = c16[i];
                    acc += uh*(cc*(cc*qq + rhg*rgh));
                }
            }
            float wt = (g < h0 + 32) ? 1.f : 2.f;   // diag tile x1, upper tiles x2
            acc *= u_g * wt;
        }
        #pragma unroll
        for (int off = 16; off; off >>= 1) acc += __shfl_xor_sync(~0u, acc, off);
        if ((tid&31) == 0) sred[tid>>5] = acc;
        __syncthreads();
        if (tid == 0) {
            float ttl = 0.f;
            #pragma unroll
            for (int i=0;i<8;i++) ttl += sred[i];
            g_part[b*NS + split] = ttl;
            __threadfence();
            int old = atomicAdd(&g_cnt[b], 1);
            sflag = (old == NS-1);
        }
        __syncthreads();
        if (sflag) {   // per-batch finalize (fixed-order sums — deterministic)
            if (tid == 0) {
                while (ldacq(&g_pdone[b]) == 0) {}
                __threadfence();
                float n2 = 0.f;
                #pragma unroll
                for (int k=0;k<NS;k++) n2 += g_part[b*NS + k];
                n2 *= 2.f;
                float nF = sqrtf(fmaxf(n2, 0.f)) + 1e-6f;
                sscale = -1.f/(nF * g_nv[b]);
                g_cnt[b] = 0;   // reset for replay
            }
            __syncthreads();
            if (tid < Dq)
                out[Bq*Dq + b*Dq + tid] = g_num[b*Dq+tid]*sscale - 0.1f*sb[b*Dq+tid];
        }
        if (tid == 0) {   // global epilogue: last pair block resets flags for replay
            int old = atomicAdd(&g_all, 1);
            if (old == NP-1) {
                g_cdone = 0;
                #pragma unroll
                for (int i=0;i<Bq;i++) { g_bdone[i] = 0; g_pdone[i] = 0; }
                g_all = 0;
            }
        }
    }
}

extern "C" void kernel_launch(void* const* d_in, const int* in_sizes, int n_in,
                              void* d_out, int out_size) {
    const float* t  = (const float*)d_in[0];
    const float* sb = (const float*)d_in[1];
    const float* x0 = (const float*)d_in[2];
    const float* x1 = (const float*)d_in[3];
    const float* W1 = (const float*)d_in[4];
    const float* b1 = (const float*)d_in[5];
    const float* W2 = (const float*)d_in[6];
    float* out = (float*)d_out;

    mega<<<GRID, 256>>>(t, sb, x0, x1, W1, b1, W2, out);
}

// round 7
// speedup vs baseline: 2.6557x; 1.0741x over previous
#include <cuda_runtime.h>
#include <math.h>

typedef unsigned long long u64;
#define Bq 32
#define Dq 128
#define Hq 256
#define Oq 10
#define NCT 36                // C tile blocks (upper-tri of 8x8 tiles of 32)
#define NKB 4                 // K blocks per batch (g-quarters)
#define NS  8                 // h-splits per batch in pair phase
#define NP  (Bq*NS)           // 256 pair blocks
#define BX_P (NCT)            // 36  : P blocks start
#define BX_K (NCT+Bq)         // 68  : K blocks start
#define BX_Q (BX_K+NKB*Bq)    // 196 : pair blocks start
#define GRID (BX_Q+NP)        // 452 total (< 592 resident capacity -> 1 wave)

// Scratch (allocation-free rule: __device__ globals; zero-initialized)
__device__ float g_C[Hq*Hq];
__device__ float g_K[Bq*Oq*Hq];
__device__ __align__(16) float g_KT[Bq*Hq*12];   // K transposed: [b][g][o], stride 12
__device__ float g_u[Bq*Hq];
__device__ float g_G2p[Bq][NKB][112];
__device__ float g_num[Bq*Dq];
__device__ float g_nv[Bq];
__device__ float g_part[Bq*NS];
__device__ int   g_cdone;
__device__ int   g_udone[Bq];
__device__ int   g_kcnt[Bq];
__device__ int   g_pdone[Bq];
__device__ int   g_cnt[Bq];
__device__ int   g_all;

// ---- f32x2 packed helpers (sm_103a) ----
__device__ __forceinline__ u64 pk2(float x, float y){ u64 r; asm("mov.b64 %0,{%1,%2};" : "=l"(r) : "f"(x),"f"(y)); return r; }
__device__ __forceinline__ u64 fma2(u64 a,u64 b,u64 c){ u64 d; asm("fma.rn.f32x2 %0,%1,%2,%3;" : "=l"(d) : "l"(a),"l"(b),"l"(c)); return d; }
__device__ __forceinline__ void up2(u64 a, float&x, float&y){ asm("mov.b64 {%0,%1},%2;" : "=f"(x),"=f"(y) : "l"(a)); }
__device__ __forceinline__ float hadd2(u64 a){ float x,y; up2(a,x,y); return x+y; }
__device__ __forceinline__ int ldacq(const int* p){
    int v; asm volatile("ld.global.acquire.gpu.b32 %0, [%1];" : "=r"(v) : "l"(p) : "memory"); return v;
}
__device__ __forceinline__ void strel(int* p, int v){
    asm volatile("st.global.release.gpu.b32 [%0], %1;" :: "l"(p), "r"(v) : "memory");
}

__global__ void __launch_bounds__(256, 4)
mega(const float* __restrict__ t,  const float* __restrict__ sb,
     const float* __restrict__ x0, const float* __restrict__ x1,
     const float* __restrict__ W1, const float* __restrict__ b1,
     const float* __restrict__ W2, float* __restrict__ out)
{
    __shared__ __align__(16) float SH[9600];
    __shared__ float sred[8];
    __shared__ float sscale;
    __shared__ int   sflag;
    int tid = threadIdx.x;
    int bx  = blockIdx.x;

    // ================= Phase C: C = W1^T W1 (36 symmetric tiles) =================
    if (bx < NCT) {
        int r = bx, ti = 0;
        while (r >= 8 - ti) { r -= 8 - ti; ti++; }
        int tj = ti + r;
        float* shA = SH;            // [128][36]
        float* shB = SH + 4608;     // [128][36]
        for (int i = tid; i < 4096; i += 256) {
            int d = i >> 5, col = i & 31;
            shA[d*36+col] = W1[d*Hq + ti*32 + col];
            shB[d*36+col] = W1[d*Hq + tj*32 + col];
        }
        __syncthreads();
        int jb = tid & 31, a0 = (tid >> 5) * 4;
        float acc0=0.f, acc1=0.f, acc2=0.f, acc3=0.f;
        #pragma unroll 4
        for (int d = 0; d < Dq; d++) {
            float4 av = *(const float4*)(shA + d*36 + a0);
            float  bv = shB[d*36 + jb];
            acc0 += av.x*bv; acc1 += av.y*bv; acc2 += av.z*bv; acc3 += av.w*bv;
        }
        int h0 = ti*32, g0 = tj*32;
        g_C[(h0+a0+0)*Hq + g0+jb] = acc0;
        g_C[(h0+a0+1)*Hq + g0+jb] = acc1;
        g_C[(h0+a0+2)*Hq + g0+jb] = acc2;
        g_C[(h0+a0+3)*Hq + g0+jb] = acc3;
        if (ti != tj) {
            g_C[(g0+jb)*Hq + h0+a0+0] = acc0;
            g_C[(g0+jb)*Hq + h0+a0+1] = acc1;
            g_C[(g0+jb)*Hq + h0+a0+2] = acc2;
            g_C[(g0+jb)*Hq + h0+a0+3] = acc3;
        }
        __threadfence();
        __syncthreads();
        if (tid == 0) atomicAdd(&g_cdone, 1);
        return;
    }

    // ================= Phase P: 32 C-free per-batch blocks (overlaps C) =================
    if (bx < BX_K) {
        int b = bx - BX_P;
        float2* sxv = (float2*)SH;        // [128] (x,v)
        float*  ss  = SH + 256;
        float*  sq  = SH + 512;           // u*w^2
        float*  sp  = SH + 768;
        float*  sc  = SH + 1024;          // [16]

        float tt = t[0];
        float window = 4.f*tt*(1.f-tt);
        if (tid < Dq) {
            float dev = sb[b*Dq + tid];
            float a0v = x0[b*Dq + tid];
            sxv[tid] = make_float2(a0v + tt*(x1[b*Dq+tid]-a0v) + window*dev,
                                   sb[Bq*Dq + b*Dq + tid]);
        }
        __syncthreads();

        u64 zw = pk2(b1[tid], 0.f);
        const u64* sxv64 = (const u64*)sxv;
        #pragma unroll 4
        for (int d = 0; d < Dq; d++) {
            float wv = W1[d*Hq + tid];
            zw = fma2(sxv64[d], pk2(wv,wv), zw);
        }
        float z, w; up2(zw, z, w);
        float th = tanhf(z);
        float s  = 1.f - th*th;
        float u  = -2.f*th*s;
        ss[tid] = s;
        sq[tid] = u*w*w;
        float w2r[Oq];
        #pragma unroll
        for (int o=0;o<Oq;o++) w2r[o] = W2[tid*Oq+o];

        if (tid < 32) {   // ||v||
            float acc = 0.f;
            for (int d = tid; d < Dq; d += 32) { float v = sxv[d].y; acc += v*v; }
            #pragma unroll
            for (int o = 16; o; o >>= 1) acc += __shfl_xor_sync(~0u, acc, o);
            if (tid == 0) g_nv[b] = sqrtf(acc) + 1e-6f;
        }
        __syncthreads();

        // c_o = sum_h W2[h][o] u_h w_h^2   (warp per o)
        int warp = tid>>5, lane = tid&31;
        for (int o = warp; o < Oq; o += 8) {
            float acc = 0.f;
            #pragma unroll
            for (int k = 0; k < 8; k++) { int h = lane + 32*k; acc += W2[h*Oq+o]*sq[h]; }
            #pragma unroll
            for (int off = 16; off; off >>= 1) acc += __shfl_xor_sync(~0u, acc, off);
            if (lane == 0) sc[o] = acc;
        }
        __syncthreads();
        {
            float p = 0.f;
            #pragma unroll
            for (int o=0;o<Oq;o++) p += w2r[o]*sc[o];
            sp[tid] = ss[tid]*p;
        }
        __syncthreads();
        // num_i = sum_g sp_g W1[i][g]  (warp-per-row, 4 concurrent rows)
        for (int r0 = 0; r0 < 16; r0 += 4) {
            int i0 = warp*16 + r0;
            float a0=0.f,a1=0.f,a2=0.f,a3=0.f;
            #pragma unroll
            for (int k = 0; k < 8; k++) {
                int gg = lane + 32*k;
                float spv = sp[gg];
                a0 += spv*W1[(i0+0)*Hq+gg];
                a1 += spv*W1[(i0+1)*Hq+gg];
                a2 += spv*W1[(i0+2)*Hq+gg];
                a3 += spv*W1[(i0+3)*Hq+gg];
            }
            #pragma unroll
            for (int off = 16; off; off >>= 1) {
                a0 += __shfl_xor_sync(~0u,a0,off); a1 += __shfl_xor_sync(~0u,a1,off);
                a2 += __shfl_xor_sync(~0u,a2,off); a3 += __shfl_xor_sync(~0u,a3,off);
            }
            if (lane == 0) {
                g_num[b*Dq+i0+0]=a0; g_num[b*Dq+i0+1]=a1;
                g_num[b*Dq+i0+2]=a2; g_num[b*Dq+i0+3]=a3;
            }
        }
        __threadfence();
        __syncthreads();
        if (tid == 0) strel(&g_pdone[b], 1);
        return;
    }

    // ================= Phase K: 128 blocks (4 per batch, g-quarters) =================
    if (bx < BX_Q) {
        int kb = bx - BX_K;
        int b = kb >> 2, quarter = kb & 3, gbase = quarter * 64;
        float* sx    = SH;          // [128]
        float* ssw2  = SH + 256;    // [256][12]
        float* spart = SH + 3328;   // [256][12] partial K (g-local x h-quarter)
        float* sKTc  = SH + 6400;   // [64][12] combined K (this g-quarter)

        float tt = t[0];
        float window = 4.f*tt*(1.f-tt);
        if (tid < Dq) {
            float dev = sb[b*Dq + tid];
            float a0v = x0[b*Dq + tid];
            sx[tid] = a0v + tt*(x1[b*Dq+tid]-a0v) + window*dev;
        }
        __syncthreads();

        // z with 4 independent accumulator chains (MLP~16)
        float z0 = b1[tid], z1 = 0.f, z2 = 0.f, z3 = 0.f;
        #pragma unroll 4
        for (int d = 0; d < Dq; d += 4) {
            z0 += sx[d+0]*W1[(d+0)*Hq + tid];
            z1 += sx[d+1]*W1[(d+1)*Hq + tid];
            z2 += sx[d+2]*W1[(d+2)*Hq + tid];
            z3 += sx[d+3]*W1[(d+3)*Hq + tid];
        }
        float z = (z0+z1)+(z2+z3);
        float th = tanhf(z);
        float s  = 1.f - th*th;
        if (quarter == 0) g_u[b*Hq + tid] = -2.f*th*s;
        #pragma unroll
        for (int o=0;o<Oq;o++) ssw2[tid*12+o] = s*W2[tid*Oq+o];
        __syncthreads();
        // early-u release (free: overlapped by the C wait below)
        if (quarter == 0 && tid == 0) { __threadfence(); strel(&g_udone[b], 1); }

        if (tid == 0) { while (ldacq(&g_cdone) < NCT) {} }   // wait C (z overlapped it)
        __syncthreads();

        // partial K: thread -> g = gbase+(tid&63), h in [hbase,hbase+64), double-buffered
        {
            int g = gbase + (tid & 63);
            int hbase = (tid >> 6) * 64;
            float cb[2][16];
            #pragma unroll
            for (int i=0;i<16;i++) cb[0][i] = g_C[(hbase+i)*Hq + g];
            u64 k0=0,k1v=0,k2v=0,k3=0,k4=0;
            #pragma unroll
            for (int ch = 0; ch < 4; ch++) {
                int cur = ch & 1;
                if (ch < 3) {
                    #pragma unroll
                    for (int i=0;i<16;i++) cb[cur^1][i] = g_C[(hbase+(ch+1)*16+i)*Hq + g];
                }
                #pragma unroll
                for (int i=0;i<16;i++) {
                    float c = cb[cur][i];
                    u64 bb = pk2(c,c);
                    const u64* pp = (const u64*)(ssw2 + (hbase+ch*16+i)*12);
                    k0=fma2(pp[0],bb,k0); k1v=fma2(pp[1],bb,k1v); k2v=fma2(pp[2],bb,k2v);
                    k3=fma2(pp[3],bb,k3); k4=fma2(pp[4],bb,k4);
                }
            }
            u64* pd = (u64*)(spart + tid*12);
            pd[0]=k0; pd[1]=k1v; pd[2]=k2v; pd[3]=k3; pd[4]=k4;
        }
        __syncthreads();
        if (tid < 64) {   // combine 4 h-quarters (fixed order), publish K (both layouts)
            float kv[Oq];
            #pragma unroll
            for (int o=0;o<Oq;o++) {
                kv[o] = spart[tid*12+o] + spart[(tid+64)*12+o]
                      + spart[(tid+128)*12+o] + spart[(tid+192)*12+o];
                sKTc[tid*12+o] = kv[o];
                g_K[(b*Oq+o)*Hq + gbase + tid] = kv[o];
            }
            u64* ktd = (u64*)(g_KT + (b*Hq + gbase + tid)*12);
            #pragma unroll
            for (int i=0;i<5;i++) ktd[i] = pk2(kv[2*i], kv[2*i+1]);
        }
        __syncthreads();
        // G2 partial over this g-quarter (chain length 64, 2 accumulators)
        if (tid < Oq*Oq) {
            int o = tid/Oq, p = tid%Oq;
            float accA = 0.f, accB = 0.f;
            #pragma unroll 4
            for (int gg = 0; gg < 64; gg += 2) {
                accA += sKTc[gg*12+o]     * ssw2[(gbase+gg)*12+p];
                accB += sKTc[(gg+1)*12+o] * ssw2[(gbase+gg+1)*12+p];
            }
            g_G2p[b][quarter][tid] = accA + accB;
        }
        __threadfence();
        __syncthreads();
        if (tid == 0) atomicAdd(&g_kcnt[b], 1);   // direct release (no combine stage)
        return;
    }

    // ===== Phase Q: 256 pair blocks (symmetric tiles; G2 self-summed; staged prefetch) =====
    {
        int pb = bx - BX_Q;
        int b = pb >> 3, split = pb & (NS-1);
        int h0 = split * 32;
        int g = tid;
        float* sWU  = SH;         // [32][12] W2 row + u_h at [10]
        float* sKTp = SH + 384;   // [32][12]
        float* sG2  = SH + 768;   // [100]

        bool active = (g >= h0);  // warp-uniform (h0 multiple of 32)

        // ---- stage A: no dependencies ----
        float w2g[Oq];
        #pragma unroll
        for (int o=0;o<Oq;o++) w2g[o] = W2[g*Oq+o];
        if (split == 0 && tid < Dq)
            out[b*Dq + tid] = sb[Bq*Dq + b*Dq + tid];   // velocity half
        if (tid >= 128 && tid < 160) {
            int hh = tid - 128, h = h0 + hh;
            #pragma unroll
            for (int o=0;o<Oq;o++) sWU[hh*12+o] = W2[h*Oq+o];
        }

        // ---- stage B: u available early (during K phase) ----
        if (tid == 0) { while (ldacq(&g_udone[b]) == 0) {} }
        __syncthreads();
        float u_g = g_u[b*Hq + g];
        if (tid >= 128 && tid < 160) {
            int hh = tid - 128;
            sWU[hh*12+10] = g_u[b*Hq + h0 + hh];
        }

        // ---- stage C: K + G2 partials ready ----
        if (tid == 0) { while (ldacq(&g_kcnt[b]) < NKB) {} }
        __syncthreads();
        if (tid < Oq*Oq)
            sG2[tid] = g_G2p[b][0][tid] + g_G2p[b][1][tid]
                     + g_G2p[b][2][tid] + g_G2p[b][3][tid];
        if (tid >= 128 && tid < 160) {
            int hh = tid - 128;
            const u64* src = (const u64*)(g_KT + (b*Hq + h0 + hh)*12);
            u64* dst = (u64*)(sKTp + hh*12);
            #pragma unroll
            for (int i=0;i<5;i++) dst[i] = src[i];
        }
        u64 kcp[5];
        if (active) {
            const u64* kt = (const u64*)(g_KT + (b*Hq + g)*12);
            #pragma unroll
            for (int i=0;i<5;i++) kcp[i] = kt[i];
        }
        __syncthreads();

        float acc = 0.f;
        if (active) {
            u64 wgp[5], w2p[5];
            #pragma unroll
            for (int i=0;i<5;i++){
                float a0 = 0.f, a1 = 0.f;
                #pragma unroll
                for (int p=0;p<Oq;p++){
                    a0 += sG2[(2*i)*Oq+p]*w2g[p];
                    a1 += sG2[(2*i+1)*Oq+p]*w2g[p];
                }
                wgp[i] = pk2(a0,a1);
                w2p[i] = pk2(w2g[2*i], w2g[2*i+1]);
            }

            // main loop: 4 chunks of 8, double-buffered C loads
            float cbA[8], cbB[8];
            #pragma unroll
            for (int i=0;i<8;i++) cbA[i] = g_C[(h0+i)*Hq + g];
            #pragma unroll
            for (int ch = 0; ch < 4; ch++) {
                float* cur = (ch & 1) ? cbB : cbA;
                float* nxt = (ch & 1) ? cbA : cbB;
                if (ch < 3) {
                    #pragma unroll
                    for (int i=0;i<8;i++) nxt[i] = g_C[(h0+(ch+1)*8+i)*Hq + g];
                }
                #pragma unroll
                for (int i=0;i<8;i++) {
                    int hh = ch*8 + i;
                    const u64* pa  = (const u64*)(sWU  + hh*12);
                    const u64* pb2 = (const u64*)(sKTp + hh*12);
                    u64 q2=0, r2=0, s2=0;
                    #pragma unroll
                    for (int j=0;j<5;j++){
                        q2 = fma2(pa[j],  wgp[j], q2);
                        r2 = fma2(pa[j],  kcp[j], r2);
                        s2 = fma2(pb2[j], w2p[j], s2);
                    }
                    float qq = hadd2(q2), rhg = hadd2(r2), rgh = hadd2(s2);
                    float uh = sWU[hh*12+10];
                    float cc = cur[i];
                    acc += uh*(cc*(cc*qq + rhg*rgh));
                }
            }
            float wt = (g < h0 + 32) ? 1.f : 2.f;   // diag tile x1, upper tiles x2
            acc *= u_g * wt;
        }
        #pragma unroll
        for (int off = 16; off; off >>= 1) acc += __shfl_xor_sync(~0u, acc, off);
        if ((tid&31) == 0) sred[tid>>5] = acc;
        __syncthreads();
        if (tid == 0) {
            float ttl = 0.f;
            #pragma unroll
            for (int i=0;i<8;i++) ttl += sred[i];
            g_part[b*NS + split] = ttl;
            __threadfence();
            int old = atomicAdd(&g_cnt[b], 1);
            sflag = (old == NS-1);
        }
        __syncthreads();
        if (sflag) {   // per-batch finalize (fixed-order sums — deterministic)
            if (tid == 0) {
                while (ldacq(&g_pdone[b]) == 0) {}
                __threadfence();
                float n2 = 0.f;
                #pragma unroll
                for (int k=0;k<NS;k++) n2 += g_part[b*NS + k];
                n2 *= 2.f;
                float nF = sqrtf(fmaxf(n2, 0.f)) + 1e-6f;
                sscale = -1.f/(nF * g_nv[b]);
                g_cnt[b]  = 0;   // reset for replay
                g_kcnt[b] = 0;
            }
            __syncthreads();
            if (tid < Dq)
                out[Bq*Dq + b*Dq + tid] = g_num[b*Dq+tid]*sscale - 0.1f*sb[b*Dq+tid];
        }
        if (tid == 0) {   // global epilogue: last pair block resets shared flags for replay
            int old = atomicAdd(&g_all, 1);
            if (old == NP-1) {
                g_cdone = 0;
                #pragma unroll
                for (int i=0;i<Bq;i++) { g_pdone[i] = 0; g_udone[i] = 0; }
                g_all = 0;
            }
        }
    }
}

extern "C" void kernel_launch(void* const* d_in, const int* in_sizes, int n_in,
                              void* d_out, int out_size) {
    const float* t  = (const float*)d_in[0];
    const float* sb = (const float*)d_in[1];
    const float* x0 = (const float*)d_in[2];
    const float* x1 = (const float*)d_in[3];
    const float* W1 = (const float*)d_in[4];
    const float* b1 = (const float*)d_in[5];
    const float* W2 = (const float*)d_in[6];
    float* out = (float*)d_out;

    mega<<<GRID, 256>>>(t, sb, x0, x1, W1, b1, W2, out);
}